// round 14
// baseline (speedup 1.0000x reference)
#include <cuda_runtime.h>
#include <cuda_bf16.h>
#include <cuda_fp16.h>
#include <cstdint>
#include <math.h>

// Problem constants
#define BB 8
#define SS 2048
#define DD 512
#define UU 512

#define NX ((size_t)BB * SS * DD)      // 8388608
#define NW ((size_t)DD * UU)           // 262144
#define NA ((size_t)BB * SS * SS)      // 33554432

#define SCALE 0.04419417382415922f    // 1/sqrt(512)

// ---------------------------------------------------------------------------
// Device-global scratch (no allocations allowed)
// ---------------------------------------------------------------------------
__device__ __align__(128) __nv_bfloat16 g_wqh[NW], g_wql[NW];    // Wq splits [D][U] (Mt only)
__device__ __align__(128) __nv_bfloat16 g_wkh[NW], g_wkl[NW];    // Wk splits [D][U] (Mt only)
__device__ __align__(128) __half g_xf[NX];                       // x fp16 [B*S][D]
__device__ __align__(128) __half g_wvtf[NW];                     // Wv^T fp16 [U][D]
__device__ __align__(128) __half g_mtf[NW];                      // Mt fp16 [D][D]
__device__ __align__(128) __half g_pf[NX];                       // P fp16 [B*S][D]
__device__ __align__(128) __half g_vtf[NX];                      // V^T fp16 [B][U][S]
__device__ __align__(128) __half g_af[NA];                       // E = exp(scores-m) fp16
__device__ __align__(128) float  g_is[(size_t)BB * SS];          // inv row sums

// ---------------------------------------------------------------------------
// Helpers
// ---------------------------------------------------------------------------
__device__ __forceinline__ uint32_t smem_u32(const void* p) {
    uint32_t a;
    asm("{ .reg .u64 t; cvta.to.shared.u64 t, %1; cvt.u32.u64 %0, t; }" : "=r"(a) : "l"(p));
    return a;
}
__device__ __forceinline__ uint32_t pack_h2(float a, float b) {
    __half2 h = __floats2half2_rn(a, b);
    return *reinterpret_cast<uint32_t*>(&h);
}
__device__ __forceinline__ uint32_t pack_bf2(__nv_bfloat16 a, __nv_bfloat16 b) {
    return (uint32_t)__bfloat16_as_ushort(a) | ((uint32_t)__bfloat16_as_ushort(b) << 16);
}

#define LDSM4(r0, r1, r2, r3, addr) \
    asm volatile("ldmatrix.sync.aligned.m8n8.x4.shared.b16 {%0,%1,%2,%3}, [%4];" \
        : "=r"(r0), "=r"(r1), "=r"(r2), "=r"(r3) : "r"(addr))

#define MMA16816(d, a, b) \
    asm("mma.sync.aligned.m16n8k16.row.col.f32.bf16.bf16.f32 " \
        "{%0,%1,%2,%3}, {%4,%5,%6,%7}, {%8,%9}, {%0,%1,%2,%3};" \
        : "+f"((d)[0]), "+f"((d)[1]), "+f"((d)[2]), "+f"((d)[3]) \
        : "r"((a)[0]), "r"((a)[1]), "r"((a)[2]), "r"((a)[3]), \
          "r"((b)[0]), "r"((b)[1]))

#define MMAH16816(d, a, b) \
    asm("mma.sync.aligned.m16n8k16.row.col.f32.f16.f16.f32 " \
        "{%0,%1,%2,%3}, {%4,%5,%6,%7}, {%8,%9}, {%0,%1,%2,%3};" \
        : "+f"((d)[0]), "+f"((d)[1]), "+f"((d)[2]), "+f"((d)[3]) \
        : "r"((a)[0]), "r"((a)[1]), "r"((a)[2]), "r"((a)[3]), \
          "r"((b)[0]), "r"((b)[1]))

// ---------------------------------------------------------------------------
// Common tiling: 128x128 CTA tile, BK=32, 256 threads (8 warps 2x4, 64x32
// warp tile), 3-stage cp.async pipeline, 2 CTAs/SM.  64B smem rows, XOR
// swizzle phys_chunk = c ^ ((r>>1)&3).  Operands K-major; C = A * B^T.
// ---------------------------------------------------------------------------
#define ARR_B 8192                      // 128 rows * 64 bytes per array
#define STG_B 32768                     // 4 arrays per stage (bf16x3 engine)
#define SMEM_DYN (3 * STG_B)            // 98304 bytes
#define STGF_B 16384                    // 2 arrays per stage (fp16 engine)
#define SMEM_F16 (3 * STGF_B)           // 49152 bytes

template <typename T>
__device__ __forceinline__ void stage_arr(uint32_t sdst, const T* __restrict__ src,
                                          int r0, int k0, int ld, int tid) {
#pragma unroll
    for (int j = 0; j < 2; j++) {
        int idx = tid + j * 256;                  // 512 chunks of 16B
        int r = idx >> 2, c = idx & 3;
        int phys = c ^ ((r >> 1) & 3);
        uint32_t dst = sdst + (uint32_t)(r * 64 + phys * 16);
        const void* gp = (const void*)(src + (size_t)(r0 + r) * ld + k0 + c * 8);
        asm volatile("cp.async.cg.shared.global [%0], [%1], 16;" :: "r"(dst), "l"(gp));
    }
}

// ---------------------------------------------------------------------------
// bf16x3 engine — used ONLY for Mt (16 blocks).  fp16-out with alpha.
// ---------------------------------------------------------------------------
__device__ __forceinline__ void gemm_bf3(int row0, int col0,
                                         const __nv_bfloat16* __restrict__ Ah,
                                         const __nv_bfloat16* __restrict__ Al,
                                         const __nv_bfloat16* __restrict__ Bh,
                                         const __nv_bfloat16* __restrict__ Bl,
                                         int K, int lda, int ldb, float alpha,
                                         __half* __restrict__ Of, int ldo) {
    extern __shared__ __nv_bfloat16 smem[];

    const int tid  = threadIdx.x;
    const int warp = tid >> 5;
    const int lane = tid & 31;
    const int wm = (warp >> 2) * 64;
    const int wn = (warp & 3) * 32;

    const uint32_t sbase = smem_u32(smem);

    const int aRow = wm + ((lane >> 3) & 1) * 8 + (lane & 7);
    const uint32_t aOff = (uint32_t)(aRow * 64);
    const uint32_t aS   = (uint32_t)((aRow >> 1) & 3);
    const uint32_t aK   = (uint32_t)(lane >> 4);
    const int bRow = wn + ((lane >> 4) & 1) * 8 + (lane & 7);
    const uint32_t bOff = (uint32_t)(bRow * 64);
    const uint32_t bS   = (uint32_t)((bRow >> 1) & 3);
    const uint32_t bK   = (uint32_t)((lane >> 3) & 1);

    float acc[4][4][4];
#pragma unroll
    for (int i = 0; i < 4; i++)
#pragma unroll
        for (int j = 0; j < 4; j++)
#pragma unroll
            for (int e = 0; e < 4; e++) acc[i][j][e] = 0.0f;

    const int niter = K >> 5;

#pragma unroll
    for (int s = 0; s < 2; s++) {
        uint32_t sb = sbase + (uint32_t)(s * STG_B);
        stage_arr(sb + 0 * ARR_B, Ah, row0, s * 32, lda, tid);
        stage_arr(sb + 1 * ARR_B, Al, row0, s * 32, lda, tid);
        stage_arr(sb + 2 * ARR_B, Bh, col0, s * 32, ldb, tid);
        stage_arr(sb + 3 * ARR_B, Bl, col0, s * 32, ldb, tid);
        asm volatile("cp.async.commit_group;" ::: "memory");
    }

    int buf = 0;
    for (int it = 0; it < niter; it++) {
        if (it + 1 < niter) {
            asm volatile("cp.async.wait_group 1;" ::: "memory");
        } else {
            asm volatile("cp.async.wait_group 0;" ::: "memory");
        }
        __syncthreads();
        if (it + 2 < niter) {
            int nb = buf + 2; if (nb >= 3) nb -= 3;
            uint32_t sb = sbase + (uint32_t)(nb * STG_B);
            int k0 = (it + 2) << 5;
            stage_arr(sb + 0 * ARR_B, Ah, row0, k0, lda, tid);
            stage_arr(sb + 1 * ARR_B, Al, row0, k0, lda, tid);
            stage_arr(sb + 2 * ARR_B, Bh, col0, k0, ldb, tid);
            stage_arr(sb + 3 * ARR_B, Bl, col0, k0, ldb, tid);
            asm volatile("cp.async.commit_group;" ::: "memory");
        }

        const uint32_t base = sbase + (uint32_t)(buf * STG_B);
        const uint32_t pAh = base + 0 * ARR_B + aOff;
        const uint32_t pAl = base + 1 * ARR_B + aOff;
        const uint32_t pBh = base + 2 * ARR_B + bOff;
        const uint32_t pBl = base + 3 * ARR_B + bOff;

#pragma unroll
        for (int ks = 0; ks < 2; ks++) {
            const uint32_t koA = (((ks * 2 + aK) ^ aS) << 4);
            const uint32_t koB = (((ks * 2 + bK) ^ bS) << 4);
            uint32_t ah[4][4], al[4][4];
            uint32_t bh[4][2], bl[4][2];
#pragma unroll
            for (int jp = 0; jp < 2; jp++) {
                LDSM4(bh[2 * jp][0], bh[2 * jp][1], bh[2 * jp + 1][0], bh[2 * jp + 1][1],
                      pBh + jp * 1024 + koB);
                LDSM4(bl[2 * jp][0], bl[2 * jp][1], bl[2 * jp + 1][0], bl[2 * jp + 1][1],
                      pBl + jp * 1024 + koB);
            }
#pragma unroll
            for (int i = 0; i < 4; i++) {
                LDSM4(ah[i][0], ah[i][1], ah[i][2], ah[i][3], pAh + i * 1024 + koA);
                LDSM4(al[i][0], al[i][1], al[i][2], al[i][3], pAl + i * 1024 + koA);
            }
#pragma unroll
            for (int i = 0; i < 4; i++)
#pragma unroll
                for (int j = 0; j < 4; j++) MMA16816(acc[i][j], ah[i], bh[j]);
#pragma unroll
            for (int i = 0; i < 4; i++)
#pragma unroll
                for (int j = 0; j < 4; j++) MMA16816(acc[i][j], ah[i], bl[j]);
#pragma unroll
            for (int i = 0; i < 4; i++)
#pragma unroll
                for (int j = 0; j < 4; j++) MMA16816(acc[i][j], al[i], bh[j]);
        }
        buf++; if (buf == 3) buf = 0;
    }

    const int er = lane >> 2;
    const int ec = (lane & 3) * 2;
#pragma unroll
    for (int i = 0; i < 4; i++)
#pragma unroll
        for (int j = 0; j < 4; j++) {
            size_t r = (size_t)(row0 + wm + i * 16 + er);
            int c = col0 + wn + j * 8 + ec;
            *reinterpret_cast<uint32_t*>(&Of[r * ldo + c]) =
                pack_h2(acc[i][j][0] * alpha, acc[i][j][1] * alpha);
            *reinterpret_cast<uint32_t*>(&Of[(r + 8) * ldo + c]) =
                pack_h2(acc[i][j][2] * alpha, acc[i][j][3] * alpha);
        }
}

// ---------------------------------------------------------------------------
// fp16 single-term engine.  MODE 0: fp32 store.  MODE 3: fp16 direct store.
// MODE 4: fp16 TRANSPOSED store (per-batch V^T layout, ldo = SS).
// ---------------------------------------------------------------------------
template <int MODE>
__device__ __forceinline__ void gemm_f16(int row0, int col0,
                                         const __half* __restrict__ Af,
                                         const __half* __restrict__ Bf,
                                         int K, int lda, int ldb,
                                         float* __restrict__ Cf, int ldc,
                                         __half* __restrict__ Of, int ldo) {
    extern __shared__ __nv_bfloat16 smem[];

    const int tid  = threadIdx.x;
    const int warp = tid >> 5;
    const int lane = tid & 31;
    const int wm = (warp >> 2) * 64;
    const int wn = (warp & 3) * 32;

    const uint32_t sbase = smem_u32(smem);

    const int aRow = wm + ((lane >> 3) & 1) * 8 + (lane & 7);
    const uint32_t aOff = (uint32_t)(aRow * 64);
    const uint32_t aS   = (uint32_t)((aRow >> 1) & 3);
    const uint32_t aK   = (uint32_t)(lane >> 4);
    const int bRow = wn + ((lane >> 4) & 1) * 8 + (lane & 7);
    const uint32_t bOff = (uint32_t)(bRow * 64);
    const uint32_t bS   = (uint32_t)((bRow >> 1) & 3);
    const uint32_t bK   = (uint32_t)((lane >> 3) & 1);

    float acc[4][4][4];
#pragma unroll
    for (int i = 0; i < 4; i++)
#pragma unroll
        for (int j = 0; j < 4; j++)
#pragma unroll
            for (int e = 0; e < 4; e++) acc[i][j][e] = 0.0f;

    const int niter = K >> 5;

#pragma unroll
    for (int s = 0; s < 2; s++) {
        uint32_t sb = sbase + (uint32_t)(s * STGF_B);
        stage_arr(sb + 0 * ARR_B, Af, row0, s * 32, lda, tid);
        stage_arr(sb + 1 * ARR_B, Bf, col0, s * 32, ldb, tid);
        asm volatile("cp.async.commit_group;" ::: "memory");
    }

    int buf = 0;
    for (int it = 0; it < niter; it++) {
        if (it + 1 < niter) {
            asm volatile("cp.async.wait_group 1;" ::: "memory");
        } else {
            asm volatile("cp.async.wait_group 0;" ::: "memory");
        }
        __syncthreads();
        if (it + 2 < niter) {
            int nb = buf + 2; if (nb >= 3) nb -= 3;
            uint32_t sb = sbase + (uint32_t)(nb * STGF_B);
            int k0 = (it + 2) << 5;
            stage_arr(sb + 0 * ARR_B, Af, row0, k0, lda, tid);
            stage_arr(sb + 1 * ARR_B, Bf, col0, k0, ldb, tid);
            asm volatile("cp.async.commit_group;" ::: "memory");
        }

        const uint32_t base = sbase + (uint32_t)(buf * STGF_B);
        const uint32_t pA = base + 0 * ARR_B + aOff;
        const uint32_t pB = base + 1 * ARR_B + bOff;

#pragma unroll
        for (int ks = 0; ks < 2; ks++) {
            const uint32_t koA = (((ks * 2 + aK) ^ aS) << 4);
            const uint32_t koB = (((ks * 2 + bK) ^ bS) << 4);
            uint32_t ah[4][4];
            uint32_t bh[4][2];
#pragma unroll
            for (int jp = 0; jp < 2; jp++) {
                LDSM4(bh[2 * jp][0], bh[2 * jp][1], bh[2 * jp + 1][0], bh[2 * jp + 1][1],
                      pB + jp * 1024 + koB);
            }
#pragma unroll
            for (int i = 0; i < 4; i++) {
                LDSM4(ah[i][0], ah[i][1], ah[i][2], ah[i][3], pA + i * 1024 + koA);
            }
#pragma unroll
            for (int i = 0; i < 4; i++)
#pragma unroll
                for (int j = 0; j < 4; j++) MMAH16816(acc[i][j], ah[i], bh[j]);
        }
        buf++; if (buf == 3) buf = 0;
    }

    const int er = lane >> 2;
    const int ec = (lane & 3) * 2;

    if constexpr (MODE == 0) {
#pragma unroll
        for (int i = 0; i < 4; i++)
#pragma unroll
            for (int j = 0; j < 4; j++) {
                size_t r = (size_t)(row0 + wm + i * 16 + er);
                int c = col0 + wn + j * 8 + ec;
                *reinterpret_cast<float2*>(&Cf[r * ldc + c]) =
                    make_float2(acc[i][j][0], acc[i][j][1]);
                *reinterpret_cast<float2*>(&Cf[(r + 8) * ldc + c]) =
                    make_float2(acc[i][j][2], acc[i][j][3]);
            }
    } else if constexpr (MODE == 3) {
#pragma unroll
        for (int i = 0; i < 4; i++)
#pragma unroll
            for (int j = 0; j < 4; j++) {
                size_t r = (size_t)(row0 + wm + i * 16 + er);
                int c = col0 + wn + j * 8 + ec;
                *reinterpret_cast<uint32_t*>(&Of[r * ldo + c]) =
                    pack_h2(acc[i][j][0], acc[i][j][1]);
                *reinterpret_cast<uint32_t*>(&Of[(r + 8) * ldo + c]) =
                    pack_h2(acc[i][j][2], acc[i][j][3]);
            }
    } else {
        // MODE 4: fp16 transposed store (V^T); row0 indexes tokens [B*S]
        __syncthreads();
        float* ew = (float*)(smem + warp * 768);
        const int b = row0 >> 11;                  // SS == 2048
        __half* Ob = Of + (size_t)b * UU * SS;
#pragma unroll
        for (int i = 0; i < 4; i++)
#pragma unroll
            for (int jp = 0; jp < 2; jp++) {
                int j0 = 2 * jp, j1 = 2 * jp + 1;
                ew[er * 24 + ec]            = acc[i][j0][0];
                ew[er * 24 + ec + 1]        = acc[i][j0][1];
                ew[(er + 8) * 24 + ec]      = acc[i][j0][2];
                ew[(er + 8) * 24 + ec + 1]  = acc[i][j0][3];
                ew[er * 24 + 8 + ec]        = acc[i][j1][0];
                ew[er * 24 + 8 + ec + 1]    = acc[i][j1][1];
                ew[(er + 8) * 24 + 8 + ec]     = acc[i][j1][2];
                ew[(er + 8) * 24 + 8 + ec + 1] = acc[i][j1][3];
                __syncwarp();
                if (lane < 16) {
                    int u = lane;
                    float v[16];
#pragma unroll
                    for (int r = 0; r < 16; r++) v[r] = ew[r * 24 + u];
                    uint32_t hw[8];
#pragma unroll
                    for (int e = 0; e < 8; e++) hw[e] = pack_h2(v[2 * e], v[2 * e + 1]);
                    int s0 = (row0 & 2047) + wm + i * 16;
                    size_t idx = (size_t)(col0 + wn + jp * 16 + u) * SS + s0;
                    uint4 h0, h1;
                    h0.x = hw[0]; h0.y = hw[1]; h0.z = hw[2]; h0.w = hw[3];
                    h1.x = hw[4]; h1.y = hw[5]; h1.z = hw[6]; h1.w = hw[7];
                    *reinterpret_cast<uint4*>(&Ob[idx])     = h0;
                    *reinterpret_cast<uint4*>(&Ob[idx + 8]) = h1;
                }
                __syncwarp();
            }
    }
}

// ---------------------------------------------------------------------------
// context engine: fp16 GEMM (E @ V^T), epilogue scaled by inv_s[row]; CTAs
// with col0==0 also emit normalized fp32 attn from the staged E tiles.
// ---------------------------------------------------------------------------
__device__ __forceinline__ void gemm_ctx(int row0, int col0,
                                         const __half* __restrict__ Ef,
                                         const __half* __restrict__ Vf,
                                         float* __restrict__ attnB,   // batch base
                                         const float* __restrict__ isB,
                                         float* __restrict__ Cf, int ldc) {
    extern __shared__ __nv_bfloat16 smem[];
    __shared__ float sIs[128];

    const int tid  = threadIdx.x;
    const int warp = tid >> 5;
    const int lane = tid & 31;
    const int wm = (warp >> 2) * 64;
    const int wn = (warp & 3) * 32;

    const uint32_t sbase = smem_u32(smem);
    const bool writeAttn = (col0 == 0);

    if (tid < 128) sIs[tid] = isB[row0 + tid];

    const int aRow = wm + ((lane >> 3) & 1) * 8 + (lane & 7);
    const uint32_t aOff = (uint32_t)(aRow * 64);
    const uint32_t aS   = (uint32_t)((aRow >> 1) & 3);
    const uint32_t aK   = (uint32_t)(lane >> 4);
    const int bRow = wn + ((lane >> 4) & 1) * 8 + (lane & 7);
    const uint32_t bOff = (uint32_t)(bRow * 64);
    const uint32_t bS   = (uint32_t)((bRow >> 1) & 3);
    const uint32_t bK   = (uint32_t)((lane >> 3) & 1);

    float acc[4][4][4];
#pragma unroll
    for (int i = 0; i < 4; i++)
#pragma unroll
        for (int j = 0; j < 4; j++)
#pragma unroll
            for (int e = 0; e < 4; e++) acc[i][j][e] = 0.0f;

    const int niter = SS >> 5;   // K = 2048

#pragma unroll
    for (int s = 0; s < 2; s++) {
        uint32_t sb = sbase + (uint32_t)(s * STGF_B);
        stage_arr(sb + 0 * ARR_B, Ef, row0, s * 32, SS, tid);
        stage_arr(sb + 1 * ARR_B, Vf, col0, s * 32, SS, tid);
        asm volatile("cp.async.commit_group;" ::: "memory");
    }

    int buf = 0;
    for (int it = 0; it < niter; it++) {
        if (it + 1 < niter) {
            asm volatile("cp.async.wait_group 1;" ::: "memory");
        } else {
            asm volatile("cp.async.wait_group 0;" ::: "memory");
        }
        __syncthreads();
        if (it + 2 < niter) {
            int nb = buf + 2; if (nb >= 3) nb -= 3;
            uint32_t sb = sbase + (uint32_t)(nb * STGF_B);
            int k0 = (it + 2) << 5;
            stage_arr(sb + 0 * ARR_B, Ef, row0, k0, SS, tid);
            stage_arr(sb + 1 * ARR_B, Vf, col0, k0, SS, tid);
            asm volatile("cp.async.commit_group;" ::: "memory");
        }

        // Emit normalized fp32 attn for this k-slab from the staged E tile.
        if (writeAttn) {
            const char* sA = (const char*)smem + buf * STGF_B;
            int k0 = it << 5;
#pragma unroll
            for (int j = 0; j < 2; j++) {
                int id2 = tid + j * 256;
                int r = id2 >> 2, c = id2 & 3;
                int phys = c ^ ((r >> 1) & 3);
                uint4 hv = *reinterpret_cast<const uint4*>(sA + r * 64 + phys * 16);
                float is = sIs[r];
                __half2 h0 = *reinterpret_cast<__half2*>(&hv.x);
                __half2 h1 = *reinterpret_cast<__half2*>(&hv.y);
                __half2 h2 = *reinterpret_cast<__half2*>(&hv.z);
                __half2 h3 = *reinterpret_cast<__half2*>(&hv.w);
                float4 f0, f1;
                f0.x = __low2float(h0) * is; f0.y = __high2float(h0) * is;
                f0.z = __low2float(h1) * is; f0.w = __high2float(h1) * is;
                f1.x = __low2float(h2) * is; f1.y = __high2float(h2) * is;
                f1.z = __low2float(h3) * is; f1.w = __high2float(h3) * is;
                float* dst = &attnB[(size_t)(row0 + r) * SS + k0 + c * 8];
                *reinterpret_cast<float4*>(dst)     = f0;
                *reinterpret_cast<float4*>(dst + 4) = f1;
            }
        }

        const uint32_t base = sbase + (uint32_t)(buf * STGF_B);
        const uint32_t pA = base + 0 * ARR_B + aOff;
        const uint32_t pB = base + 1 * ARR_B + bOff;

#pragma unroll
        for (int ks = 0; ks < 2; ks++) {
            const uint32_t koA = (((ks * 2 + aK) ^ aS) << 4);
            const uint32_t koB = (((ks * 2 + bK) ^ bS) << 4);
            uint32_t ah[4][4];
            uint32_t bh[4][2];
#pragma unroll
            for (int jp = 0; jp < 2; jp++) {
                LDSM4(bh[2 * jp][0], bh[2 * jp][1], bh[2 * jp + 1][0], bh[2 * jp + 1][1],
                      pB + jp * 1024 + koB);
            }
#pragma unroll
            for (int i = 0; i < 4; i++) {
                LDSM4(ah[i][0], ah[i][1], ah[i][2], ah[i][3], pA + i * 1024 + koA);
            }
#pragma unroll
            for (int i = 0; i < 4; i++)
#pragma unroll
                for (int j = 0; j < 4; j++) MMAH16816(acc[i][j], ah[i], bh[j]);
        }
        buf++; if (buf == 3) buf = 0;
    }

    // epilogue: fp32 store scaled by inv_s
    const int er = lane >> 2;
    const int ec = (lane & 3) * 2;
#pragma unroll
    for (int i = 0; i < 4; i++) {
        float i0 = sIs[wm + i * 16 + er];
        float i1 = sIs[wm + i * 16 + er + 8];
#pragma unroll
        for (int j = 0; j < 4; j++) {
            size_t r = (size_t)(row0 + wm + i * 16 + er);
            int c = col0 + wn + j * 8 + ec;
            *reinterpret_cast<float2*>(&Cf[r * ldc + c]) =
                make_float2(acc[i][j][0] * i0, acc[i][j][1] * i0);
            *reinterpret_cast<float2*>(&Cf[(r + 8) * ldc + c]) =
                make_float2(acc[i][j][2] * i1, acc[i][j][3] * i1);
        }
    }
}

// ---------------------------------------------------------------------------
// GEMM kernel wrappers (2 CTAs/SM)
// ---------------------------------------------------------------------------
__global__ __launch_bounds__(256, 2) void vmt_kernel() {
    int id = blockIdx.x;
    if (id < 512) {
        int row0 = (id >> 2) * 128;
        int col0 = (id & 3) * 128;
        gemm_f16<4>(row0, col0, g_xf, g_wvtf, DD, DD, DD,
                    nullptr, 0, g_vtf, SS);
    } else {
        int id2 = id - 512;
        int row0 = (id2 >> 2) * 128;
        int col0 = (id2 & 3) * 128;
        gemm_bf3(row0, col0, g_wkh, g_wkl, g_wqh, g_wql, UU, UU, UU, SCALE,
                 g_mtf, DD);
    }
}

__global__ __launch_bounds__(256, 2) void p_kernel() {
    gemm_f16<3>(blockIdx.y * 128, blockIdx.x * 128,
                g_xf, g_mtf, DD, DD, DD,
                nullptr, 0, g_pf, DD);
}

__global__ __launch_bounds__(256, 2) void scores_kernel(float* __restrict__ attn) {
    const size_t zo = (size_t)blockIdx.z * SS * DD;
    gemm_f16<0>(blockIdx.y * 128, blockIdx.x * 128,
                g_pf + zo, g_xf + zo, DD, DD, DD,
                attn + (size_t)blockIdx.z * SS * SS, SS, nullptr, 0);
}

__global__ __launch_bounds__(256, 2) void context_kernel(float* __restrict__ ctx,
                                                         float* __restrict__ attn) {
    const size_t z = blockIdx.z;
    gemm_ctx(blockIdx.y * 128, blockIdx.x * 128,
             g_af + z * (size_t)SS * SS, g_vtf + z * (size_t)UU * SS,
             attn + z * (size_t)SS * SS, g_is + z * SS,
             ctx + z * (size_t)SS * UU, UU);
}

// ---------------------------------------------------------------------------
// Elementwise kernels
// ---------------------------------------------------------------------------
__global__ __launch_bounds__(256) void split_x_kernel(const float* __restrict__ in) {
    int i = blockIdx.x * 256 + threadIdx.x;
    float4 v = reinterpret_cast<const float4*>(in)[i];
    uint2 fp;
    fp.x = pack_h2(v.x, v.y);
    fp.y = pack_h2(v.z, v.w);
    reinterpret_cast<uint2*>(g_xf)[i] = fp;
}

__global__ __launch_bounds__(256) void splitW_kernel(const float* __restrict__ wq,
                                                     const float* __restrict__ wk) {
    const float* src = (blockIdx.y == 0) ? wq : wk;
    __nv_bfloat16* oh = (blockIdx.y == 0) ? g_wqh : g_wkh;
    __nv_bfloat16* ol = (blockIdx.y == 0) ? g_wql : g_wkl;
    int i = blockIdx.x * 256 + threadIdx.x;
    float4 v = reinterpret_cast<const float4*>(src)[i];
    __nv_bfloat16 h0 = __float2bfloat16(v.x), h1 = __float2bfloat16(v.y);
    __nv_bfloat16 h2 = __float2bfloat16(v.z), h3 = __float2bfloat16(v.w);
    uint2 hp, lp;
    hp.x = pack_bf2(h0, h1); hp.y = pack_bf2(h2, h3);
    lp.x = pack_bf2(__float2bfloat16(v.x - __bfloat162float(h0)),
                    __float2bfloat16(v.y - __bfloat162float(h1)));
    lp.y = pack_bf2(__float2bfloat16(v.z - __bfloat162float(h2)),
                    __float2bfloat16(v.w - __bfloat162float(h3)));
    reinterpret_cast<uint2*>(oh)[i] = hp;
    reinterpret_cast<uint2*>(ol)[i] = lp;
}

__global__ void wsplitT_kernel(const float* __restrict__ wv) {
    __shared__ float t[32][33];
    const int u0 = blockIdx.x * 32, d0 = blockIdx.y * 32;
    const int tx = threadIdx.x, ty = threadIdx.y;
#pragma unroll
    for (int p = 0; p < 4; p++)
        t[ty + p * 8][tx] = wv[(size_t)(d0 + ty + p * 8) * UU + u0 + tx];
    __syncthreads();
#pragma unroll
    for (int p = 0; p < 4; p++) {
        float v = t[tx][ty + p * 8];
        size_t idx = (size_t)(u0 + ty + p * 8) * DD + d0 + tx;
        g_wvtf[idx] = __float2half_rn(v);
    }
}

__device__ __forceinline__ float warp_max(float v) {
#pragma unroll
    for (int o = 16; o > 0; o >>= 1) v = fmaxf(v, __shfl_xor_sync(0xffffffffu, v, o));
    return v;
}
__device__ __forceinline__ float warp_sum(float v) {
#pragma unroll
    for (int o = 16; o > 0; o >>= 1) v += __shfl_xor_sync(0xffffffffu, v, o);
    return v;
}

// Row softmax -> UNNORMALIZED fp16 E + inv row-sum.  No fp32 rewrite.
__global__ __launch_bounds__(256) void softmax_e_kernel(const float* __restrict__ attn) {
    const size_t rowbase = (size_t)blockIdx.x * SS;
    const float* p = attn + rowbase;
    const int tid = threadIdx.x;
    const int c0 = tid * 8;
    __shared__ float red[8];

    float4 va = *reinterpret_cast<const float4*>(&p[c0]);
    float4 vb = *reinterpret_cast<const float4*>(&p[c0 + 4]);
    float v[8] = {va.x, va.y, va.z, va.w, vb.x, vb.y, vb.z, vb.w};

    float m = v[0];
#pragma unroll
    for (int j = 1; j < 8; j++) m = fmaxf(m, v[j]);
    m = warp_max(m);
    if ((tid & 31) == 0) red[tid >> 5] = m;
    __syncthreads();
    if (tid < 32) {
        float t = (tid < 8) ? red[tid] : -INFINITY;
        t = warp_max(t);
        if (tid == 0) red[0] = t;
    }
    __syncthreads();
    m = red[0];

    float s = 0.0f;
#pragma unroll
    for (int j = 0; j < 8; j++) { v[j] = __expf(v[j] - m); s += v[j]; }
    s = warp_sum(s);
    __syncthreads();
    if ((tid & 31) == 0) red[tid >> 5] = s;
    __syncthreads();
    if (tid < 32) {
        float t = (tid < 8) ? red[tid] : 0.0f;
        t = warp_sum(t);
        if (tid == 0) red[0] = t;
    }
    __syncthreads();

    if (tid == 0) g_is[blockIdx.x] = 1.0f / red[0];

    uint4 fp;
    fp.x = pack_h2(v[0], v[1]); fp.y = pack_h2(v[2], v[3]);
    fp.z = pack_h2(v[4], v[5]); fp.w = pack_h2(v[6], v[7]);
    *reinterpret_cast<uint4*>(&g_af[rowbase + c0]) = fp;
}

// ---------------------------------------------------------------------------
extern "C" void kernel_launch(void* const* d_in, const int* in_sizes, int n_in,
                              void* d_out, int out_size) {
    const float* x  = (const float*)d_in[0];   // [B,S,D]
    const float* wq = (const float*)d_in[1];   // [D,U]
    const float* wk = (const float*)d_in[2];
    const float* wv = (const float*)d_in[3];

    float* out  = (float*)d_out;
    float* ctx  = out;                         // [B,S,U]
    float* attn = out + NX;                    // [B,S,S]

    cudaFuncSetAttribute(vmt_kernel,     cudaFuncAttributeMaxDynamicSharedMemorySize, SMEM_DYN);
    cudaFuncSetAttribute(p_kernel,       cudaFuncAttributeMaxDynamicSharedMemorySize, SMEM_F16);
    cudaFuncSetAttribute(scores_kernel,  cudaFuncAttributeMaxDynamicSharedMemorySize, SMEM_F16);
    cudaFuncSetAttribute(context_kernel, cudaFuncAttributeMaxDynamicSharedMemorySize, SMEM_F16);

    // 1. splits: x -> fp16, Wq/Wk -> bf16 pairs (Mt only), Wv -> fp16 transposed
    split_x_kernel<<<(int)(NX / 4 / 256), 256>>>(x);
    splitW_kernel<<<dim3((int)(NW / 4 / 256), 2), 256>>>(wq, wk);
    wsplitT_kernel<<<dim3(UU / 32, DD / 32), dim3(32, 8)>>>(wv);

    // 2. V^T fp16 = (x @ Wv)^T  and  Mt fp16 = scale * Wk @ Wq^T (bf16x3 math)
    vmt_kernel<<<dim3(528), 256, SMEM_DYN>>>();

    // 3. P fp16 = x @ Mt^T  [16384x512]
    p_kernel<<<dim3(4, 128), 256, SMEM_F16>>>();

    // 4. raw scores = P @ x^T per batch (fp32, into attn region)
    scores_kernel<<<dim3(16, 16, BB), 256, SMEM_F16>>>(attn);

    // 5. softmax stats: E = exp(v - m) fp16 + inv_s
    softmax_e_kernel<<<dim3(BB * SS), 256>>>(attn);

    // 6. context = (E @ V) * inv_s; col0==0 CTAs also write normalized fp32 attn
    context_kernel<<<dim3(4, 16, BB), 256, SMEM_F16>>>(ctx, attn);
}

// round 15
// speedup vs baseline: 1.0491x; 1.0491x over previous
#include <cuda_runtime.h>
#include <cuda_bf16.h>
#include <cuda_fp16.h>
#include <cstdint>
#include <math.h>

// Problem constants
#define BB 8
#define SS 2048
#define DD 512
#define UU 512

#define NX ((size_t)BB * SS * DD)      // 8388608
#define NW ((size_t)DD * UU)           // 262144
#define NA ((size_t)BB * SS * SS)      // 33554432

#define SCALE 0.04419417382415922f    // 1/sqrt(512)

// ---------------------------------------------------------------------------
// Device-global scratch (no allocations allowed)
// ---------------------------------------------------------------------------
__device__ __align__(128) __nv_bfloat16 g_wqh[NW], g_wql[NW];    // Wq splits [D][U] (Mt only)
__device__ __align__(128) __nv_bfloat16 g_wkh[NW], g_wkl[NW];    // Wk splits [D][U] (Mt only)
__device__ __align__(128) __half g_xf[NX];                       // x fp16 [B*S][D]
__device__ __align__(128) __half g_wvtf[NW];                     // Wv^T fp16 [U][D]
__device__ __align__(128) __half g_mtf[NW];                      // Mt fp16 [D][D]
__device__ __align__(128) __half g_pf[NX];                       // P fp16 [B*S][D]
__device__ __align__(128) __half g_vtf[NX];                      // V^T fp16 [B][U][S]
__device__ __align__(128) __half g_af[NA];                       // E = exp(scores-m) fp16
__device__ __align__(128) float  g_is[(size_t)BB * SS];          // inv row sums

// ---------------------------------------------------------------------------
// Helpers
// ---------------------------------------------------------------------------
__device__ __forceinline__ uint32_t smem_u32(const void* p) {
    uint32_t a;
    asm("{ .reg .u64 t; cvta.to.shared.u64 t, %1; cvt.u32.u64 %0, t; }" : "=r"(a) : "l"(p));
    return a;
}
__device__ __forceinline__ uint32_t pack_h2(float a, float b) {
    __half2 h = __floats2half2_rn(a, b);
    return *reinterpret_cast<uint32_t*>(&h);
}
__device__ __forceinline__ uint32_t pack_bf2(__nv_bfloat16 a, __nv_bfloat16 b) {
    return (uint32_t)__bfloat16_as_ushort(a) | ((uint32_t)__bfloat16_as_ushort(b) << 16);
}

#define LDSM4(r0, r1, r2, r3, addr) \
    asm volatile("ldmatrix.sync.aligned.m8n8.x4.shared.b16 {%0,%1,%2,%3}, [%4];" \
        : "=r"(r0), "=r"(r1), "=r"(r2), "=r"(r3) : "r"(addr))

#define MMA16816(d, a, b) \
    asm("mma.sync.aligned.m16n8k16.row.col.f32.bf16.bf16.f32 " \
        "{%0,%1,%2,%3}, {%4,%5,%6,%7}, {%8,%9}, {%0,%1,%2,%3};" \
        : "+f"((d)[0]), "+f"((d)[1]), "+f"((d)[2]), "+f"((d)[3]) \
        : "r"((a)[0]), "r"((a)[1]), "r"((a)[2]), "r"((a)[3]), \
          "r"((b)[0]), "r"((b)[1]))

#define MMAH16816(d, a, b) \
    asm("mma.sync.aligned.m16n8k16.row.col.f32.f16.f16.f32 " \
        "{%0,%1,%2,%3}, {%4,%5,%6,%7}, {%8,%9}, {%0,%1,%2,%3};" \
        : "+f"((d)[0]), "+f"((d)[1]), "+f"((d)[2]), "+f"((d)[3]) \
        : "r"((a)[0]), "r"((a)[1]), "r"((a)[2]), "r"((a)[3]), \
          "r"((b)[0]), "r"((b)[1]))

// ---------------------------------------------------------------------------
// Common tiling: 128x128 CTA tile, BK=32, 256 threads (8 warps 2x4, 64x32
// warp tile), 3-stage cp.async pipeline, 2 CTAs/SM.  64B smem rows, XOR
// swizzle phys_chunk = c ^ ((r>>1)&3).  Operands K-major; C = A * B^T.
// ---------------------------------------------------------------------------
#define ARR_B 8192                      // 128 rows * 64 bytes per array
#define STG_B 32768                     // 4 arrays per stage (bf16x3 engine)
#define SMEM_DYN (3 * STG_B)            // 98304 bytes
#define STGF_B 16384                    // 2 arrays per stage (fp16 engine)
#define SMEM_F16 (3 * STGF_B)           // 49152 bytes

template <typename T>
__device__ __forceinline__ void stage_arr(uint32_t sdst, const T* __restrict__ src,
                                          int r0, int k0, int ld, int tid) {
#pragma unroll
    for (int j = 0; j < 2; j++) {
        int idx = tid + j * 256;                  // 512 chunks of 16B
        int r = idx >> 2, c = idx & 3;
        int phys = c ^ ((r >> 1) & 3);
        uint32_t dst = sdst + (uint32_t)(r * 64 + phys * 16);
        const void* gp = (const void*)(src + (size_t)(r0 + r) * ld + k0 + c * 8);
        asm volatile("cp.async.cg.shared.global [%0], [%1], 16;" :: "r"(dst), "l"(gp));
    }
}

// ---------------------------------------------------------------------------
// bf16x3 engine — used ONLY for Mt (16 blocks).  fp16-out with alpha.
// ---------------------------------------------------------------------------
__device__ __forceinline__ void gemm_bf3(int row0, int col0,
                                         const __nv_bfloat16* __restrict__ Ah,
                                         const __nv_bfloat16* __restrict__ Al,
                                         const __nv_bfloat16* __restrict__ Bh,
                                         const __nv_bfloat16* __restrict__ Bl,
                                         int K, int lda, int ldb, float alpha,
                                         __half* __restrict__ Of, int ldo) {
    extern __shared__ __nv_bfloat16 smem[];

    const int tid  = threadIdx.x;
    const int warp = tid >> 5;
    const int lane = tid & 31;
    const int wm = (warp >> 2) * 64;
    const int wn = (warp & 3) * 32;

    const uint32_t sbase = smem_u32(smem);

    const int aRow = wm + ((lane >> 3) & 1) * 8 + (lane & 7);
    const uint32_t aOff = (uint32_t)(aRow * 64);
    const uint32_t aS   = (uint32_t)((aRow >> 1) & 3);
    const uint32_t aK   = (uint32_t)(lane >> 4);
    const int bRow = wn + ((lane >> 4) & 1) * 8 + (lane & 7);
    const uint32_t bOff = (uint32_t)(bRow * 64);
    const uint32_t bS   = (uint32_t)((bRow >> 1) & 3);
    const uint32_t bK   = (uint32_t)((lane >> 3) & 1);

    float acc[4][4][4];
#pragma unroll
    for (int i = 0; i < 4; i++)
#pragma unroll
        for (int j = 0; j < 4; j++)
#pragma unroll
            for (int e = 0; e < 4; e++) acc[i][j][e] = 0.0f;

    const int niter = K >> 5;

#pragma unroll
    for (int s = 0; s < 2; s++) {
        uint32_t sb = sbase + (uint32_t)(s * STG_B);
        stage_arr(sb + 0 * ARR_B, Ah, row0, s * 32, lda, tid);
        stage_arr(sb + 1 * ARR_B, Al, row0, s * 32, lda, tid);
        stage_arr(sb + 2 * ARR_B, Bh, col0, s * 32, ldb, tid);
        stage_arr(sb + 3 * ARR_B, Bl, col0, s * 32, ldb, tid);
        asm volatile("cp.async.commit_group;" ::: "memory");
    }

    int buf = 0;
    for (int it = 0; it < niter; it++) {
        if (it + 1 < niter) {
            asm volatile("cp.async.wait_group 1;" ::: "memory");
        } else {
            asm volatile("cp.async.wait_group 0;" ::: "memory");
        }
        __syncthreads();
        if (it + 2 < niter) {
            int nb = buf + 2; if (nb >= 3) nb -= 3;
            uint32_t sb = sbase + (uint32_t)(nb * STG_B);
            int k0 = (it + 2) << 5;
            stage_arr(sb + 0 * ARR_B, Ah, row0, k0, lda, tid);
            stage_arr(sb + 1 * ARR_B, Al, row0, k0, lda, tid);
            stage_arr(sb + 2 * ARR_B, Bh, col0, k0, ldb, tid);
            stage_arr(sb + 3 * ARR_B, Bl, col0, k0, ldb, tid);
            asm volatile("cp.async.commit_group;" ::: "memory");
        }

        const uint32_t base = sbase + (uint32_t)(buf * STG_B);
        const uint32_t pAh = base + 0 * ARR_B + aOff;
        const uint32_t pAl = base + 1 * ARR_B + aOff;
        const uint32_t pBh = base + 2 * ARR_B + bOff;
        const uint32_t pBl = base + 3 * ARR_B + bOff;

#pragma unroll
        for (int ks = 0; ks < 2; ks++) {
            const uint32_t koA = (((ks * 2 + aK) ^ aS) << 4);
            const uint32_t koB = (((ks * 2 + bK) ^ bS) << 4);
            uint32_t ah[4][4], al[4][4];
            uint32_t bh[4][2], bl[4][2];
#pragma unroll
            for (int jp = 0; jp < 2; jp++) {
                LDSM4(bh[2 * jp][0], bh[2 * jp][1], bh[2 * jp + 1][0], bh[2 * jp + 1][1],
                      pBh + jp * 1024 + koB);
                LDSM4(bl[2 * jp][0], bl[2 * jp][1], bl[2 * jp + 1][0], bl[2 * jp + 1][1],
                      pBl + jp * 1024 + koB);
            }
#pragma unroll
            for (int i = 0; i < 4; i++) {
                LDSM4(ah[i][0], ah[i][1], ah[i][2], ah[i][3], pAh + i * 1024 + koA);
                LDSM4(al[i][0], al[i][1], al[i][2], al[i][3], pAl + i * 1024 + koA);
            }
#pragma unroll
            for (int i = 0; i < 4; i++)
#pragma unroll
                for (int j = 0; j < 4; j++) MMA16816(acc[i][j], ah[i], bh[j]);
#pragma unroll
            for (int i = 0; i < 4; i++)
#pragma unroll
                for (int j = 0; j < 4; j++) MMA16816(acc[i][j], ah[i], bl[j]);
#pragma unroll
            for (int i = 0; i < 4; i++)
#pragma unroll
                for (int j = 0; j < 4; j++) MMA16816(acc[i][j], al[i], bh[j]);
        }
        buf++; if (buf == 3) buf = 0;
    }

    const int er = lane >> 2;
    const int ec = (lane & 3) * 2;
#pragma unroll
    for (int i = 0; i < 4; i++)
#pragma unroll
        for (int j = 0; j < 4; j++) {
            size_t r = (size_t)(row0 + wm + i * 16 + er);
            int c = col0 + wn + j * 8 + ec;
            *reinterpret_cast<uint32_t*>(&Of[r * ldo + c]) =
                pack_h2(acc[i][j][0] * alpha, acc[i][j][1] * alpha);
            *reinterpret_cast<uint32_t*>(&Of[(r + 8) * ldo + c]) =
                pack_h2(acc[i][j][2] * alpha, acc[i][j][3] * alpha);
        }
}

// ---------------------------------------------------------------------------
// fp16 single-term engine.  MODE 0: fp32 store.  MODE 3: fp16 direct store.
// MODE 4: fp16 TRANSPOSED store (per-batch V^T layout, ldo = SS).
// ---------------------------------------------------------------------------
template <int MODE>
__device__ __forceinline__ void gemm_f16(int row0, int col0,
                                         const __half* __restrict__ Af,
                                         const __half* __restrict__ Bf,
                                         int K, int lda, int ldb,
                                         float* __restrict__ Cf, int ldc,
                                         __half* __restrict__ Of, int ldo) {
    extern __shared__ __nv_bfloat16 smem[];

    const int tid  = threadIdx.x;
    const int warp = tid >> 5;
    const int lane = tid & 31;
    const int wm = (warp >> 2) * 64;
    const int wn = (warp & 3) * 32;

    const uint32_t sbase = smem_u32(smem);

    const int aRow = wm + ((lane >> 3) & 1) * 8 + (lane & 7);
    const uint32_t aOff = (uint32_t)(aRow * 64);
    const uint32_t aS   = (uint32_t)((aRow >> 1) & 3);
    const uint32_t aK   = (uint32_t)(lane >> 4);
    const int bRow = wn + ((lane >> 4) & 1) * 8 + (lane & 7);
    const uint32_t bOff = (uint32_t)(bRow * 64);
    const uint32_t bS   = (uint32_t)((bRow >> 1) & 3);
    const uint32_t bK   = (uint32_t)((lane >> 3) & 1);

    float acc[4][4][4];
#pragma unroll
    for (int i = 0; i < 4; i++)
#pragma unroll
        for (int j = 0; j < 4; j++)
#pragma unroll
            for (int e = 0; e < 4; e++) acc[i][j][e] = 0.0f;

    const int niter = K >> 5;

#pragma unroll
    for (int s = 0; s < 2; s++) {
        uint32_t sb = sbase + (uint32_t)(s * STGF_B);
        stage_arr(sb + 0 * ARR_B, Af, row0, s * 32, lda, tid);
        stage_arr(sb + 1 * ARR_B, Bf, col0, s * 32, ldb, tid);
        asm volatile("cp.async.commit_group;" ::: "memory");
    }

    int buf = 0;
    for (int it = 0; it < niter; it++) {
        if (it + 1 < niter) {
            asm volatile("cp.async.wait_group 1;" ::: "memory");
        } else {
            asm volatile("cp.async.wait_group 0;" ::: "memory");
        }
        __syncthreads();
        if (it + 2 < niter) {
            int nb = buf + 2; if (nb >= 3) nb -= 3;
            uint32_t sb = sbase + (uint32_t)(nb * STGF_B);
            int k0 = (it + 2) << 5;
            stage_arr(sb + 0 * ARR_B, Af, row0, k0, lda, tid);
            stage_arr(sb + 1 * ARR_B, Bf, col0, k0, ldb, tid);
            asm volatile("cp.async.commit_group;" ::: "memory");
        }

        const uint32_t base = sbase + (uint32_t)(buf * STGF_B);
        const uint32_t pA = base + 0 * ARR_B + aOff;
        const uint32_t pB = base + 1 * ARR_B + bOff;

#pragma unroll
        for (int ks = 0; ks < 2; ks++) {
            const uint32_t koA = (((ks * 2 + aK) ^ aS) << 4);
            const uint32_t koB = (((ks * 2 + bK) ^ bS) << 4);
            uint32_t ah[4][4];
            uint32_t bh[4][2];
#pragma unroll
            for (int jp = 0; jp < 2; jp++) {
                LDSM4(bh[2 * jp][0], bh[2 * jp][1], bh[2 * jp + 1][0], bh[2 * jp + 1][1],
                      pB + jp * 1024 + koB);
            }
#pragma unroll
            for (int i = 0; i < 4; i++) {
                LDSM4(ah[i][0], ah[i][1], ah[i][2], ah[i][3], pA + i * 1024 + koA);
            }
#pragma unroll
            for (int i = 0; i < 4; i++)
#pragma unroll
                for (int j = 0; j < 4; j++) MMAH16816(acc[i][j], ah[i], bh[j]);
        }
        buf++; if (buf == 3) buf = 0;
    }

    const int er = lane >> 2;
    const int ec = (lane & 3) * 2;

    if constexpr (MODE == 0) {
#pragma unroll
        for (int i = 0; i < 4; i++)
#pragma unroll
            for (int j = 0; j < 4; j++) {
                size_t r = (size_t)(row0 + wm + i * 16 + er);
                int c = col0 + wn + j * 8 + ec;
                *reinterpret_cast<float2*>(&Cf[r * ldc + c]) =
                    make_float2(acc[i][j][0], acc[i][j][1]);
                *reinterpret_cast<float2*>(&Cf[(r + 8) * ldc + c]) =
                    make_float2(acc[i][j][2], acc[i][j][3]);
            }
    } else if constexpr (MODE == 3) {
#pragma unroll
        for (int i = 0; i < 4; i++)
#pragma unroll
            for (int j = 0; j < 4; j++) {
                size_t r = (size_t)(row0 + wm + i * 16 + er);
                int c = col0 + wn + j * 8 + ec;
                *reinterpret_cast<uint32_t*>(&Of[r * ldo + c]) =
                    pack_h2(acc[i][j][0], acc[i][j][1]);
                *reinterpret_cast<uint32_t*>(&Of[(r + 8) * ldo + c]) =
                    pack_h2(acc[i][j][2], acc[i][j][3]);
            }
    } else {
        // MODE 4: fp16 transposed store (V^T); row0 indexes tokens [B*S]
        __syncthreads();
        float* ew = (float*)(smem + warp * 768);
        const int b = row0 >> 11;                  // SS == 2048
        __half* Ob = Of + (size_t)b * UU * SS;
#pragma unroll
        for (int i = 0; i < 4; i++)
#pragma unroll
            for (int jp = 0; jp < 2; jp++) {
                int j0 = 2 * jp, j1 = 2 * jp + 1;
                ew[er * 24 + ec]            = acc[i][j0][0];
                ew[er * 24 + ec + 1]        = acc[i][j0][1];
                ew[(er + 8) * 24 + ec]      = acc[i][j0][2];
                ew[(er + 8) * 24 + ec + 1]  = acc[i][j0][3];
                ew[er * 24 + 8 + ec]        = acc[i][j1][0];
                ew[er * 24 + 8 + ec + 1]    = acc[i][j1][1];
                ew[(er + 8) * 24 + 8 + ec]     = acc[i][j1][2];
                ew[(er + 8) * 24 + 8 + ec + 1] = acc[i][j1][3];
                __syncwarp();
                if (lane < 16) {
                    int u = lane;
                    float v[16];
#pragma unroll
                    for (int r = 0; r < 16; r++) v[r] = ew[r * 24 + u];
                    uint32_t hw[8];
#pragma unroll
                    for (int e = 0; e < 8; e++) hw[e] = pack_h2(v[2 * e], v[2 * e + 1]);
                    int s0 = (row0 & 2047) + wm + i * 16;
                    size_t idx = (size_t)(col0 + wn + jp * 16 + u) * SS + s0;
                    uint4 h0, h1;
                    h0.x = hw[0]; h0.y = hw[1]; h0.z = hw[2]; h0.w = hw[3];
                    h1.x = hw[4]; h1.y = hw[5]; h1.z = hw[6]; h1.w = hw[7];
                    *reinterpret_cast<uint4*>(&Ob[idx])     = h0;
                    *reinterpret_cast<uint4*>(&Ob[idx + 8]) = h1;
                }
                __syncwarp();
            }
    }
}

// ---------------------------------------------------------------------------
// context engine: fp16 GEMM (E @ V^T), epilogue scaled by inv_s[row].
// ALL CTAs share the attn write load: the CTA with column-tile cj writes the
// k-slabs where (it & 3) == cj (each of the 4 CTAs per row-tile stages the
// same E data, so each emits exactly 1/4 of the normalized fp32 attn).
// ---------------------------------------------------------------------------
__device__ __forceinline__ void gemm_ctx(int row0, int col0,
                                         const __half* __restrict__ Ef,
                                         const __half* __restrict__ Vf,
                                         float* __restrict__ attnB,   // batch base
                                         const float* __restrict__ isB,
                                         float* __restrict__ Cf, int ldc) {
    extern __shared__ __nv_bfloat16 smem[];
    __shared__ float sIs[128];

    const int tid  = threadIdx.x;
    const int warp = tid >> 5;
    const int lane = tid & 31;
    const int wm = (warp >> 2) * 64;
    const int wn = (warp & 3) * 32;

    const uint32_t sbase = smem_u32(smem);
    const int cj = col0 >> 7;          // 0..3: this CTA's attn-write phase

    if (tid < 128) sIs[tid] = isB[row0 + tid];

    const int aRow = wm + ((lane >> 3) & 1) * 8 + (lane & 7);
    const uint32_t aOff = (uint32_t)(aRow * 64);
    const uint32_t aS   = (uint32_t)((aRow >> 1) & 3);
    const uint32_t aK   = (uint32_t)(lane >> 4);
    const int bRow = wn + ((lane >> 4) & 1) * 8 + (lane & 7);
    const uint32_t bOff = (uint32_t)(bRow * 64);
    const uint32_t bS   = (uint32_t)((bRow >> 1) & 3);
    const uint32_t bK   = (uint32_t)((lane >> 3) & 1);

    float acc[4][4][4];
#pragma unroll
    for (int i = 0; i < 4; i++)
#pragma unroll
        for (int j = 0; j < 4; j++)
#pragma unroll
            for (int e = 0; e < 4; e++) acc[i][j][e] = 0.0f;

    const int niter = SS >> 5;   // K = 2048

#pragma unroll
    for (int s = 0; s < 2; s++) {
        uint32_t sb = sbase + (uint32_t)(s * STGF_B);
        stage_arr(sb + 0 * ARR_B, Ef, row0, s * 32, SS, tid);
        stage_arr(sb + 1 * ARR_B, Vf, col0, s * 32, SS, tid);
        asm volatile("cp.async.commit_group;" ::: "memory");
    }

    int buf = 0;
    for (int it = 0; it < niter; it++) {
        if (it + 1 < niter) {
            asm volatile("cp.async.wait_group 1;" ::: "memory");
        } else {
            asm volatile("cp.async.wait_group 0;" ::: "memory");
        }
        __syncthreads();
        if (it + 2 < niter) {
            int nb = buf + 2; if (nb >= 3) nb -= 3;
            uint32_t sb = sbase + (uint32_t)(nb * STGF_B);
            int k0 = (it + 2) << 5;
            stage_arr(sb + 0 * ARR_B, Ef, row0, k0, SS, tid);
            stage_arr(sb + 1 * ARR_B, Vf, col0, k0, SS, tid);
            asm volatile("cp.async.commit_group;" ::: "memory");
        }

        // Balanced attn emission: this CTA handles every 4th k-slab.
        if ((it & 3) == cj) {
            const char* sA = (const char*)smem + buf * STGF_B;
            int k0 = it << 5;
#pragma unroll
            for (int j = 0; j < 2; j++) {
                int id2 = tid + j * 256;
                int r = id2 >> 2, c = id2 & 3;
                int phys = c ^ ((r >> 1) & 3);
                uint4 hv = *reinterpret_cast<const uint4*>(sA + r * 64 + phys * 16);
                float is = sIs[r];
                __half2 h0 = *reinterpret_cast<__half2*>(&hv.x);
                __half2 h1 = *reinterpret_cast<__half2*>(&hv.y);
                __half2 h2 = *reinterpret_cast<__half2*>(&hv.z);
                __half2 h3 = *reinterpret_cast<__half2*>(&hv.w);
                float4 f0, f1;
                f0.x = __low2float(h0) * is; f0.y = __high2float(h0) * is;
                f0.z = __low2float(h1) * is; f0.w = __high2float(h1) * is;
                f1.x = __low2float(h2) * is; f1.y = __high2float(h2) * is;
                f1.z = __low2float(h3) * is; f1.w = __high2float(h3) * is;
                float* dst = &attnB[(size_t)(row0 + r) * SS + k0 + c * 8];
                *reinterpret_cast<float4*>(dst)     = f0;
                *reinterpret_cast<float4*>(dst + 4) = f1;
            }
        }

        const uint32_t base = sbase + (uint32_t)(buf * STGF_B);
        const uint32_t pA = base + 0 * ARR_B + aOff;
        const uint32_t pB = base + 1 * ARR_B + bOff;

#pragma unroll
        for (int ks = 0; ks < 2; ks++) {
            const uint32_t koA = (((ks * 2 + aK) ^ aS) << 4);
            const uint32_t koB = (((ks * 2 + bK) ^ bS) << 4);
            uint32_t ah[4][4];
            uint32_t bh[4][2];
#pragma unroll
            for (int jp = 0; jp < 2; jp++) {
                LDSM4(bh[2 * jp][0], bh[2 * jp][1], bh[2 * jp + 1][0], bh[2 * jp + 1][1],
                      pB + jp * 1024 + koB);
            }
#pragma unroll
            for (int i = 0; i < 4; i++) {
                LDSM4(ah[i][0], ah[i][1], ah[i][2], ah[i][3], pA + i * 1024 + koA);
            }
#pragma unroll
            for (int i = 0; i < 4; i++)
#pragma unroll
                for (int j = 0; j < 4; j++) MMAH16816(acc[i][j], ah[i], bh[j]);
        }
        buf++; if (buf == 3) buf = 0;
    }

    // epilogue: fp32 store scaled by inv_s
    const int er = lane >> 2;
    const int ec = (lane & 3) * 2;
#pragma unroll
    for (int i = 0; i < 4; i++) {
        float i0 = sIs[wm + i * 16 + er];
        float i1 = sIs[wm + i * 16 + er + 8];
#pragma unroll
        for (int j = 0; j < 4; j++) {
            size_t r = (size_t)(row0 + wm + i * 16 + er);
            int c = col0 + wn + j * 8 + ec;
            *reinterpret_cast<float2*>(&Cf[r * ldc + c]) =
                make_float2(acc[i][j][0] * i0, acc[i][j][1] * i0);
            *reinterpret_cast<float2*>(&Cf[(r + 8) * ldc + c]) =
                make_float2(acc[i][j][2] * i1, acc[i][j][3] * i1);
        }
    }
}

// ---------------------------------------------------------------------------
// GEMM kernel wrappers (2 CTAs/SM)
// ---------------------------------------------------------------------------
__global__ __launch_bounds__(256, 2) void vmt_kernel() {
    int id = blockIdx.x;
    if (id < 512) {
        int row0 = (id >> 2) * 128;
        int col0 = (id & 3) * 128;
        gemm_f16<4>(row0, col0, g_xf, g_wvtf, DD, DD, DD,
                    nullptr, 0, g_vtf, SS);
    } else {
        int id2 = id - 512;
        int row0 = (id2 >> 2) * 128;
        int col0 = (id2 & 3) * 128;
        gemm_bf3(row0, col0, g_wkh, g_wkl, g_wqh, g_wql, UU, UU, UU, SCALE,
                 g_mtf, DD);
    }
}

__global__ __launch_bounds__(256, 2) void p_kernel() {
    gemm_f16<3>(blockIdx.y * 128, blockIdx.x * 128,
                g_xf, g_mtf, DD, DD, DD,
                nullptr, 0, g_pf, DD);
}

__global__ __launch_bounds__(256, 2) void scores_kernel(float* __restrict__ attn) {
    const size_t zo = (size_t)blockIdx.z * SS * DD;
    gemm_f16<0>(blockIdx.y * 128, blockIdx.x * 128,
                g_pf + zo, g_xf + zo, DD, DD, DD,
                attn + (size_t)blockIdx.z * SS * SS, SS, nullptr, 0);
}

__global__ __launch_bounds__(256, 2) void context_kernel(float* __restrict__ ctx,
                                                         float* __restrict__ attn) {
    const size_t z = blockIdx.z;
    gemm_ctx(blockIdx.y * 128, blockIdx.x * 128,
             g_af + z * (size_t)SS * SS, g_vtf + z * (size_t)UU * SS,
             attn + z * (size_t)SS * SS, g_is + z * SS,
             ctx + z * (size_t)SS * UU, UU);
}

// ---------------------------------------------------------------------------
// Elementwise kernels
// ---------------------------------------------------------------------------
__global__ __launch_bounds__(256) void split_x_kernel(const float* __restrict__ in) {
    int i = blockIdx.x * 256 + threadIdx.x;
    float4 v = reinterpret_cast<const float4*>(in)[i];
    uint2 fp;
    fp.x = pack_h2(v.x, v.y);
    fp.y = pack_h2(v.z, v.w);
    reinterpret_cast<uint2*>(g_xf)[i] = fp;
}

__global__ __launch_bounds__(256) void splitW_kernel(const float* __restrict__ wq,
                                                     const float* __restrict__ wk) {
    const float* src = (blockIdx.y == 0) ? wq : wk;
    __nv_bfloat16* oh = (blockIdx.y == 0) ? g_wqh : g_wkh;
    __nv_bfloat16* ol = (blockIdx.y == 0) ? g_wql : g_wkl;
    int i = blockIdx.x * 256 + threadIdx.x;
    float4 v = reinterpret_cast<const float4*>(src)[i];
    __nv_bfloat16 h0 = __float2bfloat16(v.x), h1 = __float2bfloat16(v.y);
    __nv_bfloat16 h2 = __float2bfloat16(v.z), h3 = __float2bfloat16(v.w);
    uint2 hp, lp;
    hp.x = pack_bf2(h0, h1); hp.y = pack_bf2(h2, h3);
    lp.x = pack_bf2(__float2bfloat16(v.x - __bfloat162float(h0)),
                    __float2bfloat16(v.y - __bfloat162float(h1)));
    lp.y = pack_bf2(__float2bfloat16(v.z - __bfloat162float(h2)),
                    __float2bfloat16(v.w - __bfloat162float(h3)));
    reinterpret_cast<uint2*>(oh)[i] = hp;
    reinterpret_cast<uint2*>(ol)[i] = lp;
}

__global__ void wsplitT_kernel(const float* __restrict__ wv) {
    __shared__ float t[32][33];
    const int u0 = blockIdx.x * 32, d0 = blockIdx.y * 32;
    const int tx = threadIdx.x, ty = threadIdx.y;
#pragma unroll
    for (int p = 0; p < 4; p++)
        t[ty + p * 8][tx] = wv[(size_t)(d0 + ty + p * 8) * UU + u0 + tx];
    __syncthreads();
#pragma unroll
    for (int p = 0; p < 4; p++) {
        float v = t[tx][ty + p * 8];
        size_t idx = (size_t)(u0 + ty + p * 8) * DD + d0 + tx;
        g_wvtf[idx] = __float2half_rn(v);
    }
}

__device__ __forceinline__ float warp_max(float v) {
#pragma unroll
    for (int o = 16; o > 0; o >>= 1) v = fmaxf(v, __shfl_xor_sync(0xffffffffu, v, o));
    return v;
}
__device__ __forceinline__ float warp_sum(float v) {
#pragma unroll
    for (int o = 16; o > 0; o >>= 1) v += __shfl_xor_sync(0xffffffffu, v, o);
    return v;
}

// Row softmax -> UNNORMALIZED fp16 E + inv row-sum.  No fp32 rewrite.
__global__ __launch_bounds__(256) void softmax_e_kernel(const float* __restrict__ attn) {
    const size_t rowbase = (size_t)blockIdx.x * SS;
    const float* p = attn + rowbase;
    const int tid = threadIdx.x;
    const int c0 = tid * 8;
    __shared__ float red[8];

    float4 va = *reinterpret_cast<const float4*>(&p[c0]);
    float4 vb = *reinterpret_cast<const float4*>(&p[c0 + 4]);
    float v[8] = {va.x, va.y, va.z, va.w, vb.x, vb.y, vb.z, vb.w};

    float m = v[0];
#pragma unroll
    for (int j = 1; j < 8; j++) m = fmaxf(m, v[j]);
    m = warp_max(m);
    if ((tid & 31) == 0) red[tid >> 5] = m;
    __syncthreads();
    if (tid < 32) {
        float t = (tid < 8) ? red[tid] : -INFINITY;
        t = warp_max(t);
        if (tid == 0) red[0] = t;
    }
    __syncthreads();
    m = red[0];

    float s = 0.0f;
#pragma unroll
    for (int j = 0; j < 8; j++) { v[j] = __expf(v[j] - m); s += v[j]; }
    s = warp_sum(s);
    __syncthreads();
    if ((tid & 31) == 0) red[tid >> 5] = s;
    __syncthreads();
    if (tid < 32) {
        float t = (tid < 8) ? red[tid] : 0.0f;
        t = warp_sum(t);
        if (tid == 0) red[0] = t;
    }
    __syncthreads();

    if (tid == 0) g_is[blockIdx.x] = 1.0f / red[0];

    uint4 fp;
    fp.x = pack_h2(v[0], v[1]); fp.y = pack_h2(v[2], v[3]);
    fp.z = pack_h2(v[4], v[5]); fp.w = pack_h2(v[6], v[7]);
    *reinterpret_cast<uint4*>(&g_af[rowbase + c0]) = fp;
}

// ---------------------------------------------------------------------------
extern "C" void kernel_launch(void* const* d_in, const int* in_sizes, int n_in,
                              void* d_out, int out_size) {
    const float* x  = (const float*)d_in[0];   // [B,S,D]
    const float* wq = (const float*)d_in[1];   // [D,U]
    const float* wk = (const float*)d_in[2];
    const float* wv = (const float*)d_in[3];

    float* out  = (float*)d_out;
    float* ctx  = out;                         // [B,S,U]
    float* attn = out + NX;                    // [B,S,S]

    cudaFuncSetAttribute(vmt_kernel,     cudaFuncAttributeMaxDynamicSharedMemorySize, SMEM_DYN);
    cudaFuncSetAttribute(p_kernel,       cudaFuncAttributeMaxDynamicSharedMemorySize, SMEM_F16);
    cudaFuncSetAttribute(scores_kernel,  cudaFuncAttributeMaxDynamicSharedMemorySize, SMEM_F16);
    cudaFuncSetAttribute(context_kernel, cudaFuncAttributeMaxDynamicSharedMemorySize, SMEM_F16);

    // 1. splits: x -> fp16, Wq/Wk -> bf16 pairs (Mt only), Wv -> fp16 transposed
    split_x_kernel<<<(int)(NX / 4 / 256), 256>>>(x);
    splitW_kernel<<<dim3((int)(NW / 4 / 256), 2), 256>>>(wq, wk);
    wsplitT_kernel<<<dim3(UU / 32, DD / 32), dim3(32, 8)>>>(wv);

    // 2. V^T fp16 = (x @ Wv)^T  and  Mt fp16 = scale * Wk @ Wq^T (bf16x3 math)
    vmt_kernel<<<dim3(528), 256, SMEM_DYN>>>();

    // 3. P fp16 = x @ Mt^T  [16384x512]
    p_kernel<<<dim3(4, 128), 256, SMEM_F16>>>();

    // 4. raw scores = P @ x^T per batch (fp32, into attn region)
    scores_kernel<<<dim3(16, 16, BB), 256, SMEM_F16>>>(attn);

    // 5. softmax stats: E = exp(v - m) fp16 + inv_s
    softmax_e_kernel<<<dim3(BB * SS), 256>>>(attn);

    // 6. context = (E @ V) * inv_s; attn write balanced across all 4 col-CTAs
    context_kernel<<<dim3(4, 16, BB), 256, SMEM_F16>>>(ctx, attn);
}

// round 16
// speedup vs baseline: 1.1213x; 1.0688x over previous
#include <cuda_runtime.h>
#include <cuda_bf16.h>
#include <cuda_fp16.h>
#include <cstdint>
#include <math.h>

// Problem constants
#define BB 8
#define SS 2048
#define DD 512
#define UU 512

#define NX ((size_t)BB * SS * DD)      // 8388608
#define NW ((size_t)DD * UU)           // 262144
#define NA ((size_t)BB * SS * SS)      // 33554432

#define SCALE 0.04419417382415922f    // 1/sqrt(512)

// ---------------------------------------------------------------------------
// Device-global scratch (no allocations allowed)
// ---------------------------------------------------------------------------
__device__ __align__(128) __nv_bfloat16 g_wqh[NW], g_wql[NW];    // Wq splits (Mt only)
__device__ __align__(128) __nv_bfloat16 g_wkh[NW], g_wkl[NW];    // Wk splits (Mt only)
__device__ __align__(128) __half g_xf[NX];                       // x fp16 [B*S][D]
__device__ __align__(128) __half g_wvtf[NW];                     // Wv^T fp16 [U][D]
__device__ __align__(128) __half g_mtf[NW];                      // Mt fp16 [D][D]
__device__ __align__(128) __half g_pf[NX];                       // P fp16 [B*S][D]
__device__ __align__(128) __half g_vtf[NX];                      // V^T fp16 [B][U][S]
__device__ __align__(128) __half g_af[NA];                       // E = exp(scores) fp16
__device__ __align__(128) float  g_s[(size_t)BB * SS];           // row sums of E (atomic)

// ---------------------------------------------------------------------------
// Helpers
// ---------------------------------------------------------------------------
__device__ __forceinline__ uint32_t smem_u32(const void* p) {
    uint32_t a;
    asm("{ .reg .u64 t; cvta.to.shared.u64 t, %1; cvt.u32.u64 %0, t; }" : "=r"(a) : "l"(p));
    return a;
}
__device__ __forceinline__ uint32_t pack_h2(float a, float b) {
    __half2 h = __floats2half2_rn(a, b);
    return *reinterpret_cast<uint32_t*>(&h);
}
__device__ __forceinline__ uint32_t pack_bf2(__nv_bfloat16 a, __nv_bfloat16 b) {
    return (uint32_t)__bfloat16_as_ushort(a) | ((uint32_t)__bfloat16_as_ushort(b) << 16);
}

#define LDSM4(r0, r1, r2, r3, addr) \
    asm volatile("ldmatrix.sync.aligned.m8n8.x4.shared.b16 {%0,%1,%2,%3}, [%4];" \
        : "=r"(r0), "=r"(r1), "=r"(r2), "=r"(r3) : "r"(addr))

#define MMA16816(d, a, b) \
    asm("mma.sync.aligned.m16n8k16.row.col.f32.bf16.bf16.f32 " \
        "{%0,%1,%2,%3}, {%4,%5,%6,%7}, {%8,%9}, {%0,%1,%2,%3};" \
        : "+f"((d)[0]), "+f"((d)[1]), "+f"((d)[2]), "+f"((d)[3]) \
        : "r"((a)[0]), "r"((a)[1]), "r"((a)[2]), "r"((a)[3]), \
          "r"((b)[0]), "r"((b)[1]))

#define MMAH16816(d, a, b) \
    asm("mma.sync.aligned.m16n8k16.row.col.f32.f16.f16.f32 " \
        "{%0,%1,%2,%3}, {%4,%5,%6,%7}, {%8,%9}, {%0,%1,%2,%3};" \
        : "+f"((d)[0]), "+f"((d)[1]), "+f"((d)[2]), "+f"((d)[3]) \
        : "r"((a)[0]), "r"((a)[1]), "r"((a)[2]), "r"((a)[3]), \
          "r"((b)[0]), "r"((b)[1]))

// ---------------------------------------------------------------------------
// Common tiling: 128x128 CTA tile, BK=32, 256 threads (8 warps 2x4, 64x32
// warp tile), 3-stage cp.async pipeline, 2 CTAs/SM.  64B smem rows, XOR
// swizzle phys_chunk = c ^ ((r>>1)&3).  Operands K-major; C = A * B^T.
// ---------------------------------------------------------------------------
#define ARR_B 8192                      // 128 rows * 64 bytes per array
#define STG_B 32768                     // 4 arrays per stage (bf16x3 engine)
#define SMEM_DYN (3 * STG_B)            // 98304 bytes
#define STGF_B 16384                    // 2 arrays per stage (fp16 engine)
#define SMEM_F16 (3 * STGF_B)           // 49152 bytes

template <typename T>
__device__ __forceinline__ void stage_arr(uint32_t sdst, const T* __restrict__ src,
                                          int r0, int k0, int ld, int tid) {
#pragma unroll
    for (int j = 0; j < 2; j++) {
        int idx = tid + j * 256;                  // 512 chunks of 16B
        int r = idx >> 2, c = idx & 3;
        int phys = c ^ ((r >> 1) & 3);
        uint32_t dst = sdst + (uint32_t)(r * 64 + phys * 16);
        const void* gp = (const void*)(src + (size_t)(r0 + r) * ld + k0 + c * 8);
        asm volatile("cp.async.cg.shared.global [%0], [%1], 16;" :: "r"(dst), "l"(gp));
    }
}

// ---------------------------------------------------------------------------
// bf16x3 engine — used ONLY for Mt (16 blocks).  fp16-out with alpha.
// ---------------------------------------------------------------------------
__device__ __forceinline__ void gemm_bf3(int row0, int col0,
                                         const __nv_bfloat16* __restrict__ Ah,
                                         const __nv_bfloat16* __restrict__ Al,
                                         const __nv_bfloat16* __restrict__ Bh,
                                         const __nv_bfloat16* __restrict__ Bl,
                                         int K, int lda, int ldb, float alpha,
                                         __half* __restrict__ Of, int ldo) {
    extern __shared__ __nv_bfloat16 smem[];

    const int tid  = threadIdx.x;
    const int warp = tid >> 5;
    const int lane = tid & 31;
    const int wm = (warp >> 2) * 64;
    const int wn = (warp & 3) * 32;

    const uint32_t sbase = smem_u32(smem);

    const int aRow = wm + ((lane >> 3) & 1) * 8 + (lane & 7);
    const uint32_t aOff = (uint32_t)(aRow * 64);
    const uint32_t aS   = (uint32_t)((aRow >> 1) & 3);
    const uint32_t aK   = (uint32_t)(lane >> 4);
    const int bRow = wn + ((lane >> 4) & 1) * 8 + (lane & 7);
    const uint32_t bOff = (uint32_t)(bRow * 64);
    const uint32_t bS   = (uint32_t)((bRow >> 1) & 3);
    const uint32_t bK   = (uint32_t)((lane >> 3) & 1);

    float acc[4][4][4];
#pragma unroll
    for (int i = 0; i < 4; i++)
#pragma unroll
        for (int j = 0; j < 4; j++)
#pragma unroll
            for (int e = 0; e < 4; e++) acc[i][j][e] = 0.0f;

    const int niter = K >> 5;

#pragma unroll
    for (int s = 0; s < 2; s++) {
        uint32_t sb = sbase + (uint32_t)(s * STG_B);
        stage_arr(sb + 0 * ARR_B, Ah, row0, s * 32, lda, tid);
        stage_arr(sb + 1 * ARR_B, Al, row0, s * 32, lda, tid);
        stage_arr(sb + 2 * ARR_B, Bh, col0, s * 32, ldb, tid);
        stage_arr(sb + 3 * ARR_B, Bl, col0, s * 32, ldb, tid);
        asm volatile("cp.async.commit_group;" ::: "memory");
    }

    int buf = 0;
    for (int it = 0; it < niter; it++) {
        if (it + 1 < niter) {
            asm volatile("cp.async.wait_group 1;" ::: "memory");
        } else {
            asm volatile("cp.async.wait_group 0;" ::: "memory");
        }
        __syncthreads();
        if (it + 2 < niter) {
            int nb = buf + 2; if (nb >= 3) nb -= 3;
            uint32_t sb = sbase + (uint32_t)(nb * STG_B);
            int k0 = (it + 2) << 5;
            stage_arr(sb + 0 * ARR_B, Ah, row0, k0, lda, tid);
            stage_arr(sb + 1 * ARR_B, Al, row0, k0, lda, tid);
            stage_arr(sb + 2 * ARR_B, Bh, col0, k0, ldb, tid);
            stage_arr(sb + 3 * ARR_B, Bl, col0, k0, ldb, tid);
            asm volatile("cp.async.commit_group;" ::: "memory");
        }

        const uint32_t base = sbase + (uint32_t)(buf * STG_B);
        const uint32_t pAh = base + 0 * ARR_B + aOff;
        const uint32_t pAl = base + 1 * ARR_B + aOff;
        const uint32_t pBh = base + 2 * ARR_B + bOff;
        const uint32_t pBl = base + 3 * ARR_B + bOff;

#pragma unroll
        for (int ks = 0; ks < 2; ks++) {
            const uint32_t koA = (((ks * 2 + aK) ^ aS) << 4);
            const uint32_t koB = (((ks * 2 + bK) ^ bS) << 4);
            uint32_t ah[4][4], al[4][4];
            uint32_t bh[4][2], bl[4][2];
#pragma unroll
            for (int jp = 0; jp < 2; jp++) {
                LDSM4(bh[2 * jp][0], bh[2 * jp][1], bh[2 * jp + 1][0], bh[2 * jp + 1][1],
                      pBh + jp * 1024 + koB);
                LDSM4(bl[2 * jp][0], bl[2 * jp][1], bl[2 * jp + 1][0], bl[2 * jp + 1][1],
                      pBl + jp * 1024 + koB);
            }
#pragma unroll
            for (int i = 0; i < 4; i++) {
                LDSM4(ah[i][0], ah[i][1], ah[i][2], ah[i][3], pAh + i * 1024 + koA);
                LDSM4(al[i][0], al[i][1], al[i][2], al[i][3], pAl + i * 1024 + koA);
            }
#pragma unroll
            for (int i = 0; i < 4; i++)
#pragma unroll
                for (int j = 0; j < 4; j++) MMA16816(acc[i][j], ah[i], bh[j]);
#pragma unroll
            for (int i = 0; i < 4; i++)
#pragma unroll
                for (int j = 0; j < 4; j++) MMA16816(acc[i][j], ah[i], bl[j]);
#pragma unroll
            for (int i = 0; i < 4; i++)
#pragma unroll
                for (int j = 0; j < 4; j++) MMA16816(acc[i][j], al[i], bh[j]);
        }
        buf++; if (buf == 3) buf = 0;
    }

    const int er = lane >> 2;
    const int ec = (lane & 3) * 2;
#pragma unroll
    for (int i = 0; i < 4; i++)
#pragma unroll
        for (int j = 0; j < 4; j++) {
            size_t r = (size_t)(row0 + wm + i * 16 + er);
            int c = col0 + wn + j * 8 + ec;
            *reinterpret_cast<uint32_t*>(&Of[r * ldo + c]) =
                pack_h2(acc[i][j][0] * alpha, acc[i][j][1] * alpha);
            *reinterpret_cast<uint32_t*>(&Of[(r + 8) * ldo + c]) =
                pack_h2(acc[i][j][2] * alpha, acc[i][j][3] * alpha);
        }
}

// ---------------------------------------------------------------------------
// fp16 single-term engine.
// MODE 3: fp16 direct store.  MODE 4: fp16 TRANSPOSED store (V^T).
// MODE 5: E = exp(acc) fp16 store + fp32 row-sum atomics (scores+softmax).
// ---------------------------------------------------------------------------
template <int MODE>
__device__ __forceinline__ void gemm_f16(int row0, int col0,
                                         const __half* __restrict__ Af,
                                         const __half* __restrict__ Bf,
                                         int K, int lda, int ldb,
                                         float* __restrict__ Cf, int ldc,
                                         __half* __restrict__ Of, int ldo) {
    extern __shared__ __nv_bfloat16 smem[];

    const int tid  = threadIdx.x;
    const int warp = tid >> 5;
    const int lane = tid & 31;
    const int wm = (warp >> 2) * 64;
    const int wn = (warp & 3) * 32;

    const uint32_t sbase = smem_u32(smem);

    const int aRow = wm + ((lane >> 3) & 1) * 8 + (lane & 7);
    const uint32_t aOff = (uint32_t)(aRow * 64);
    const uint32_t aS   = (uint32_t)((aRow >> 1) & 3);
    const uint32_t aK   = (uint32_t)(lane >> 4);
    const int bRow = wn + ((lane >> 4) & 1) * 8 + (lane & 7);
    const uint32_t bOff = (uint32_t)(bRow * 64);
    const uint32_t bS   = (uint32_t)((bRow >> 1) & 3);
    const uint32_t bK   = (uint32_t)((lane >> 3) & 1);

    float acc[4][4][4];
#pragma unroll
    for (int i = 0; i < 4; i++)
#pragma unroll
        for (int j = 0; j < 4; j++)
#pragma unroll
            for (int e = 0; e < 4; e++) acc[i][j][e] = 0.0f;

    const int niter = K >> 5;

#pragma unroll
    for (int s = 0; s < 2; s++) {
        uint32_t sb = sbase + (uint32_t)(s * STGF_B);
        stage_arr(sb + 0 * ARR_B, Af, row0, s * 32, lda, tid);
        stage_arr(sb + 1 * ARR_B, Bf, col0, s * 32, ldb, tid);
        asm volatile("cp.async.commit_group;" ::: "memory");
    }

    int buf = 0;
    for (int it = 0; it < niter; it++) {
        if (it + 1 < niter) {
            asm volatile("cp.async.wait_group 1;" ::: "memory");
        } else {
            asm volatile("cp.async.wait_group 0;" ::: "memory");
        }
        __syncthreads();
        if (it + 2 < niter) {
            int nb = buf + 2; if (nb >= 3) nb -= 3;
            uint32_t sb = sbase + (uint32_t)(nb * STGF_B);
            int k0 = (it + 2) << 5;
            stage_arr(sb + 0 * ARR_B, Af, row0, k0, lda, tid);
            stage_arr(sb + 1 * ARR_B, Bf, col0, k0, ldb, tid);
            asm volatile("cp.async.commit_group;" ::: "memory");
        }

        const uint32_t base = sbase + (uint32_t)(buf * STGF_B);
        const uint32_t pA = base + 0 * ARR_B + aOff;
        const uint32_t pB = base + 1 * ARR_B + bOff;

#pragma unroll
        for (int ks = 0; ks < 2; ks++) {
            const uint32_t koA = (((ks * 2 + aK) ^ aS) << 4);
            const uint32_t koB = (((ks * 2 + bK) ^ bS) << 4);
            uint32_t ah[4][4];
            uint32_t bh[4][2];
#pragma unroll
            for (int jp = 0; jp < 2; jp++) {
                LDSM4(bh[2 * jp][0], bh[2 * jp][1], bh[2 * jp + 1][0], bh[2 * jp + 1][1],
                      pB + jp * 1024 + koB);
            }
#pragma unroll
            for (int i = 0; i < 4; i++) {
                LDSM4(ah[i][0], ah[i][1], ah[i][2], ah[i][3], pA + i * 1024 + koA);
            }
#pragma unroll
            for (int i = 0; i < 4; i++)
#pragma unroll
                for (int j = 0; j < 4; j++) MMAH16816(acc[i][j], ah[i], bh[j]);
        }
        buf++; if (buf == 3) buf = 0;
    }

    const int er = lane >> 2;
    const int ec = (lane & 3) * 2;

    if constexpr (MODE == 3) {
#pragma unroll
        for (int i = 0; i < 4; i++)
#pragma unroll
            for (int j = 0; j < 4; j++) {
                size_t r = (size_t)(row0 + wm + i * 16 + er);
                int c = col0 + wn + j * 8 + ec;
                *reinterpret_cast<uint32_t*>(&Of[r * ldo + c]) =
                    pack_h2(acc[i][j][0], acc[i][j][1]);
                *reinterpret_cast<uint32_t*>(&Of[(r + 8) * ldo + c]) =
                    pack_h2(acc[i][j][2], acc[i][j][3]);
            }
    } else if constexpr (MODE == 5) {
        // E = exp(score) fp16 + per-row fp32 sums -> atomicAdd into Cf[row]
        __shared__ float sSum[128];
        if (tid < 128) sSum[tid] = 0.0f;
        __syncthreads();
#pragma unroll
        for (int i = 0; i < 4; i++) {
            float slo = 0.0f, shi = 0.0f;
#pragma unroll
            for (int j = 0; j < 4; j++) {
                float e0 = __expf(acc[i][j][0]), e1 = __expf(acc[i][j][1]);
                float e2 = __expf(acc[i][j][2]), e3 = __expf(acc[i][j][3]);
                size_t r = (size_t)(row0 + wm + i * 16 + er);
                int c = col0 + wn + j * 8 + ec;
                *reinterpret_cast<uint32_t*>(&Of[r * ldo + c])       = pack_h2(e0, e1);
                *reinterpret_cast<uint32_t*>(&Of[(r + 8) * ldo + c]) = pack_h2(e2, e3);
                slo += e0 + e1;
                shi += e2 + e3;
            }
            // reduce across the 4 lanes sharing each row (lane groups of 4)
            slo += __shfl_xor_sync(0xffffffffu, slo, 1);
            slo += __shfl_xor_sync(0xffffffffu, slo, 2);
            shi += __shfl_xor_sync(0xffffffffu, shi, 1);
            shi += __shfl_xor_sync(0xffffffffu, shi, 2);
            if ((lane & 3) == 0) {
                atomicAdd(&sSum[wm + i * 16 + er], slo);
                atomicAdd(&sSum[wm + i * 16 + er + 8], shi);
            }
        }
        __syncthreads();
        if (tid < 128) atomicAdd(&Cf[row0 + tid], sSum[tid]);
    } else {
        // MODE 4: fp16 transposed store (V^T); row0 indexes tokens [B*S]
        __syncthreads();
        float* ew = (float*)(smem + warp * 768);
        const int b = row0 >> 11;                  // SS == 2048
        __half* Ob = Of + (size_t)b * UU * SS;
#pragma unroll
        for (int i = 0; i < 4; i++)
#pragma unroll
            for (int jp = 0; jp < 2; jp++) {
                int j0 = 2 * jp, j1 = 2 * jp + 1;
                ew[er * 24 + ec]            = acc[i][j0][0];
                ew[er * 24 + ec + 1]        = acc[i][j0][1];
                ew[(er + 8) * 24 + ec]      = acc[i][j0][2];
                ew[(er + 8) * 24 + ec + 1]  = acc[i][j0][3];
                ew[er * 24 + 8 + ec]        = acc[i][j1][0];
                ew[er * 24 + 8 + ec + 1]    = acc[i][j1][1];
                ew[(er + 8) * 24 + 8 + ec]     = acc[i][j1][2];
                ew[(er + 8) * 24 + 8 + ec + 1] = acc[i][j1][3];
                __syncwarp();
                if (lane < 16) {
                    int u = lane;
                    float v[16];
#pragma unroll
                    for (int r = 0; r < 16; r++) v[r] = ew[r * 24 + u];
                    uint32_t hw[8];
#pragma unroll
                    for (int e = 0; e < 8; e++) hw[e] = pack_h2(v[2 * e], v[2 * e + 1]);
                    int s0 = (row0 & 2047) + wm + i * 16;
                    size_t idx = (size_t)(col0 + wn + jp * 16 + u) * SS + s0;
                    uint4 h0, h1;
                    h0.x = hw[0]; h0.y = hw[1]; h0.z = hw[2]; h0.w = hw[3];
                    h1.x = hw[4]; h1.y = hw[5]; h1.z = hw[6]; h1.w = hw[7];
                    *reinterpret_cast<uint4*>(&Ob[idx])     = h0;
                    *reinterpret_cast<uint4*>(&Ob[idx + 8]) = h1;
                }
                __syncwarp();
            }
    }
}

// ---------------------------------------------------------------------------
// context engine: fp16 GEMM (E @ V^T), epilogue scaled by 1/rowsum.
// ---------------------------------------------------------------------------
__device__ __forceinline__ void gemm_ctx(int row0, int col0,
                                         const __half* __restrict__ Ef,
                                         const __half* __restrict__ Vf,
                                         const float* __restrict__ sB,
                                         float* __restrict__ Cf, int ldc) {
    extern __shared__ __nv_bfloat16 smem[];
    __shared__ float sIs[128];

    const int tid  = threadIdx.x;
    const int warp = tid >> 5;
    const int lane = tid & 31;
    const int wm = (warp >> 2) * 64;
    const int wn = (warp & 3) * 32;

    const uint32_t sbase = smem_u32(smem);

    if (tid < 128) sIs[tid] = 1.0f / sB[row0 + tid];

    const int aRow = wm + ((lane >> 3) & 1) * 8 + (lane & 7);
    const uint32_t aOff = (uint32_t)(aRow * 64);
    const uint32_t aS   = (uint32_t)((aRow >> 1) & 3);
    const uint32_t aK   = (uint32_t)(lane >> 4);
    const int bRow = wn + ((lane >> 4) & 1) * 8 + (lane & 7);
    const uint32_t bOff = (uint32_t)(bRow * 64);
    const uint32_t bS   = (uint32_t)((bRow >> 1) & 3);
    const uint32_t bK   = (uint32_t)((lane >> 3) & 1);

    float acc[4][4][4];
#pragma unroll
    for (int i = 0; i < 4; i++)
#pragma unroll
        for (int j = 0; j < 4; j++)
#pragma unroll
            for (int e = 0; e < 4; e++) acc[i][j][e] = 0.0f;

    const int niter = SS >> 5;

#pragma unroll
    for (int s = 0; s < 2; s++) {
        uint32_t sb = sbase + (uint32_t)(s * STGF_B);
        stage_arr(sb + 0 * ARR_B, Ef, row0, s * 32, SS, tid);
        stage_arr(sb + 1 * ARR_B, Vf, col0, s * 32, SS, tid);
        asm volatile("cp.async.commit_group;" ::: "memory");
    }

    int buf = 0;
    for (int it = 0; it < niter; it++) {
        if (it + 1 < niter) {
            asm volatile("cp.async.wait_group 1;" ::: "memory");
        } else {
            asm volatile("cp.async.wait_group 0;" ::: "memory");
        }
        __syncthreads();
        if (it + 2 < niter) {
            int nb = buf + 2; if (nb >= 3) nb -= 3;
            uint32_t sb = sbase + (uint32_t)(nb * STGF_B);
            int k0 = (it + 2) << 5;
            stage_arr(sb + 0 * ARR_B, Ef, row0, k0, SS, tid);
            stage_arr(sb + 1 * ARR_B, Vf, col0, k0, SS, tid);
            asm volatile("cp.async.commit_group;" ::: "memory");
        }

        const uint32_t base = sbase + (uint32_t)(buf * STGF_B);
        const uint32_t pA = base + 0 * ARR_B + aOff;
        const uint32_t pB = base + 1 * ARR_B + bOff;

#pragma unroll
        for (int ks = 0; ks < 2; ks++) {
            const uint32_t koA = (((ks * 2 + aK) ^ aS) << 4);
            const uint32_t koB = (((ks * 2 + bK) ^ bS) << 4);
            uint32_t ah[4][4];
            uint32_t bh[4][2];
#pragma unroll
            for (int jp = 0; jp < 2; jp++) {
                LDSM4(bh[2 * jp][0], bh[2 * jp][1], bh[2 * jp + 1][0], bh[2 * jp + 1][1],
                      pB + jp * 1024 + koB);
            }
#pragma unroll
            for (int i = 0; i < 4; i++) {
                LDSM4(ah[i][0], ah[i][1], ah[i][2], ah[i][3], pA + i * 1024 + koA);
            }
#pragma unroll
            for (int i = 0; i < 4; i++)
#pragma unroll
                for (int j = 0; j < 4; j++) MMAH16816(acc[i][j], ah[i], bh[j]);
        }
        buf++; if (buf == 3) buf = 0;
    }

    const int er = lane >> 2;
    const int ec = (lane & 3) * 2;
#pragma unroll
    for (int i = 0; i < 4; i++) {
        float i0 = sIs[wm + i * 16 + er];
        float i1 = sIs[wm + i * 16 + er + 8];
#pragma unroll
        for (int j = 0; j < 4; j++) {
            size_t r = (size_t)(row0 + wm + i * 16 + er);
            int c = col0 + wn + j * 8 + ec;
            *reinterpret_cast<float2*>(&Cf[r * ldc + c]) =
                make_float2(acc[i][j][0] * i0, acc[i][j][1] * i0);
            *reinterpret_cast<float2*>(&Cf[(r + 8) * ldc + c]) =
                make_float2(acc[i][j][2] * i1, acc[i][j][3] * i1);
        }
    }
}

// ---------------------------------------------------------------------------
// GEMM kernel wrappers (2 CTAs/SM)
// ---------------------------------------------------------------------------
__global__ __launch_bounds__(256, 2) void vmt_kernel() {
    int id = blockIdx.x;
    if (id < 512) {
        int row0 = (id >> 2) * 128;
        int col0 = (id & 3) * 128;
        gemm_f16<4>(row0, col0, g_xf, g_wvtf, DD, DD, DD,
                    nullptr, 0, g_vtf, SS);
    } else {
        int id2 = id - 512;
        int row0 = (id2 >> 2) * 128;
        int col0 = (id2 & 3) * 128;
        gemm_bf3(row0, col0, g_wkh, g_wkl, g_wqh, g_wql, UU, UU, UU, SCALE,
                 g_mtf, DD);
    }
}

__global__ __launch_bounds__(256, 2) void p_kernel() {
    gemm_f16<3>(blockIdx.y * 128, blockIdx.x * 128,
                g_xf, g_mtf, DD, DD, DD,
                nullptr, 0, g_pf, DD);
}

// scores + exp + row sums fused
__global__ __launch_bounds__(256, 2) void scores_kernel() {
    const size_t z = blockIdx.z;
    gemm_f16<5>(blockIdx.y * 128, blockIdx.x * 128,
                g_pf + z * SS * DD, g_xf + z * SS * DD, DD, DD, DD,
                g_s + z * SS, 0,
                g_af + z * (size_t)SS * SS, SS);
}

__global__ __launch_bounds__(256, 2) void context_kernel(float* __restrict__ ctx) {
    const size_t z = blockIdx.z;
    gemm_ctx(blockIdx.y * 128, blockIdx.x * 128,
             g_af + z * (size_t)SS * SS, g_vtf + z * (size_t)UU * SS,
             g_s + z * SS,
             ctx + z * (size_t)SS * UU, UU);
}

// ---------------------------------------------------------------------------
// Elementwise kernels
// ---------------------------------------------------------------------------
__global__ __launch_bounds__(256) void split_x_kernel(const float* __restrict__ in) {
    int i = blockIdx.x * 256 + threadIdx.x;
    float4 v = reinterpret_cast<const float4*>(in)[i];
    uint2 fp;
    fp.x = pack_h2(v.x, v.y);
    fp.y = pack_h2(v.z, v.w);
    reinterpret_cast<uint2*>(g_xf)[i] = fp;
}

__global__ __launch_bounds__(256) void splitW_kernel(const float* __restrict__ wq,
                                                     const float* __restrict__ wk) {
    const float* src = (blockIdx.y == 0) ? wq : wk;
    __nv_bfloat16* oh = (blockIdx.y == 0) ? g_wqh : g_wkh;
    __nv_bfloat16* ol = (blockIdx.y == 0) ? g_wql : g_wkl;
    int i = blockIdx.x * 256 + threadIdx.x;
    float4 v = reinterpret_cast<const float4*>(src)[i];
    __nv_bfloat16 h0 = __float2bfloat16(v.x), h1 = __float2bfloat16(v.y);
    __nv_bfloat16 h2 = __float2bfloat16(v.z), h3 = __float2bfloat16(v.w);
    uint2 hp, lp;
    hp.x = pack_bf2(h0, h1); hp.y = pack_bf2(h2, h3);
    lp.x = pack_bf2(__float2bfloat16(v.x - __bfloat162float(h0)),
                    __float2bfloat16(v.y - __bfloat162float(h1)));
    lp.y = pack_bf2(__float2bfloat16(v.z - __bfloat162float(h2)),
                    __float2bfloat16(v.w - __bfloat162float(h3)));
    reinterpret_cast<uint2*>(oh)[i] = hp;
    reinterpret_cast<uint2*>(ol)[i] = lp;
}

__global__ void wsplitT_kernel(const float* __restrict__ wv) {
    __shared__ float t[32][33];
    const int u0 = blockIdx.x * 32, d0 = blockIdx.y * 32;
    const int tx = threadIdx.x, ty = threadIdx.y;
#pragma unroll
    for (int p = 0; p < 4; p++)
        t[ty + p * 8][tx] = wv[(size_t)(d0 + ty + p * 8) * UU + u0 + tx];
    __syncthreads();
#pragma unroll
    for (int p = 0; p < 4; p++) {
        float v = t[tx][ty + p * 8];
        size_t idx = (size_t)(u0 + ty + p * 8) * DD + d0 + tx;
        g_wvtf[idx] = __float2half_rn(v);
    }
}

// Final attn: attn[row][c] = E[row][c] / s[row]  (fp32 out).  One block per row.
__global__ __launch_bounds__(256) void normalize_kernel(float* __restrict__ attn) {
    const size_t row = blockIdx.x;
    const float inv = 1.0f / g_s[row];
    const int c0 = threadIdx.x * 8;
    uint4 hv = *reinterpret_cast<const uint4*>(&g_af[row * SS + c0]);
    __half2 h0 = *reinterpret_cast<__half2*>(&hv.x);
    __half2 h1 = *reinterpret_cast<__half2*>(&hv.y);
    __half2 h2 = *reinterpret_cast<__half2*>(&hv.z);
    __half2 h3 = *reinterpret_cast<__half2*>(&hv.w);
    float4 f0, f1;
    f0.x = __low2float(h0) * inv; f0.y = __high2float(h0) * inv;
    f0.z = __low2float(h1) * inv; f0.w = __high2float(h1) * inv;
    f1.x = __low2float(h2) * inv; f1.y = __high2float(h2) * inv;
    f1.z = __low2float(h3) * inv; f1.w = __high2float(h3) * inv;
    float* dst = &attn[row * SS + c0];
    *reinterpret_cast<float4*>(dst)     = f0;
    *reinterpret_cast<float4*>(dst + 4) = f1;
}

// ---------------------------------------------------------------------------
extern "C" void kernel_launch(void* const* d_in, const int* in_sizes, int n_in,
                              void* d_out, int out_size) {
    const float* x  = (const float*)d_in[0];   // [B,S,D]
    const float* wq = (const float*)d_in[1];   // [D,U]
    const float* wk = (const float*)d_in[2];
    const float* wv = (const float*)d_in[3];

    float* out  = (float*)d_out;
    float* ctx  = out;                         // [B,S,U]
    float* attn = out + NX;                    // [B,S,S]

    cudaFuncSetAttribute(vmt_kernel,     cudaFuncAttributeMaxDynamicSharedMemorySize, SMEM_DYN);
    cudaFuncSetAttribute(p_kernel,       cudaFuncAttributeMaxDynamicSharedMemorySize, SMEM_F16);
    cudaFuncSetAttribute(scores_kernel,  cudaFuncAttributeMaxDynamicSharedMemorySize, SMEM_F16);
    cudaFuncSetAttribute(context_kernel, cudaFuncAttributeMaxDynamicSharedMemorySize, SMEM_F16);

    // 0. zero row-sum accumulators (graph-capturable async memset)
    void* sptr = nullptr;
    cudaGetSymbolAddress(&sptr, g_s);
    cudaMemsetAsync(sptr, 0, (size_t)BB * SS * sizeof(float));

    // 1. splits: x -> fp16, Wq/Wk -> bf16 pairs (Mt only), Wv -> fp16 transposed
    split_x_kernel<<<(int)(NX / 4 / 256), 256>>>(x);
    splitW_kernel<<<dim3((int)(NW / 4 / 256), 2), 256>>>(wq, wk);
    wsplitT_kernel<<<dim3(UU / 32, DD / 32), dim3(32, 8)>>>(wv);

    // 2. V^T fp16 = (x @ Wv)^T  and  Mt fp16 = scale * Wk @ Wq^T (bf16x3 math)
    vmt_kernel<<<dim3(528), 256, SMEM_DYN>>>();

    // 3. P fp16 = x @ Mt^T  [16384x512]
    p_kernel<<<dim3(4, 128), 256, SMEM_F16>>>();

    // 4. E = exp(P @ x^T) fp16 + row sums (fused scores+softmax, no max pass)
    scores_kernel<<<dim3(16, 16, BB), 256, SMEM_F16>>>();

    // 5a. fp32 attn = E / rowsum
    normalize_kernel<<<dim3(BB * SS), 256>>>(attn);

    // 5b. context = (E @ V) / rowsum
    context_kernel<<<dim3(4, 16, BB), 256, SMEM_F16>>>(ctx);
}

// round 17
// speedup vs baseline: 1.1885x; 1.0600x over previous
#include <cuda_runtime.h>
#include <cuda_bf16.h>
#include <cuda_fp16.h>
#include <cstdint>
#include <math.h>

// Problem constants
#define BB 8
#define SS 2048
#define DD 512
#define UU 512

#define NX ((size_t)BB * SS * DD)      // 8388608
#define NW ((size_t)DD * UU)           // 262144
#define NA ((size_t)BB * SS * SS)      // 33554432

#define SCALE 0.04419417382415922f    // 1/sqrt(512)

// ---------------------------------------------------------------------------
// Device-global scratch (no allocations allowed)
// ---------------------------------------------------------------------------
__device__ __align__(128) __nv_bfloat16 g_wqh[NW], g_wql[NW];    // Wq splits (Mt only)
__device__ __align__(128) __nv_bfloat16 g_wkh[NW], g_wkl[NW];    // Wk splits (Mt only)
__device__ __align__(128) __half g_xf[NX];                       // x fp16 [B*S][D]
__device__ __align__(128) __half g_wvtf[NW];                     // Wv^T fp16 [U][D]
__device__ __align__(128) __half g_mtf[NW];                      // Mt fp16 [D][D]
__device__ __align__(128) __half g_pf[NX];                       // P fp16 [B*S][D]
__device__ __align__(128) __half g_vtf[NX];                      // V^T fp16 [B][U][S]
__device__ __align__(128) __half g_af[NA];                       // E = exp(scores) fp16
__device__ __align__(128) float  g_s[(size_t)BB * SS];           // row sums of E (atomic)

// ---------------------------------------------------------------------------
// Helpers
// ---------------------------------------------------------------------------
__device__ __forceinline__ uint32_t smem_u32(const void* p) {
    uint32_t a;
    asm("{ .reg .u64 t; cvta.to.shared.u64 t, %1; cvt.u32.u64 %0, t; }" : "=r"(a) : "l"(p));
    return a;
}
__device__ __forceinline__ uint32_t pack_h2(float a, float b) {
    __half2 h = __floats2half2_rn(a, b);
    return *reinterpret_cast<uint32_t*>(&h);
}
__device__ __forceinline__ uint32_t pack_bf2(__nv_bfloat16 a, __nv_bfloat16 b) {
    return (uint32_t)__bfloat16_as_ushort(a) | ((uint32_t)__bfloat16_as_ushort(b) << 16);
}

#define LDSM4(r0, r1, r2, r3, addr) \
    asm volatile("ldmatrix.sync.aligned.m8n8.x4.shared.b16 {%0,%1,%2,%3}, [%4];" \
        : "=r"(r0), "=r"(r1), "=r"(r2), "=r"(r3) : "r"(addr))

#define MMA16816(d, a, b) \
    asm("mma.sync.aligned.m16n8k16.row.col.f32.bf16.bf16.f32 " \
        "{%0,%1,%2,%3}, {%4,%5,%6,%7}, {%8,%9}, {%0,%1,%2,%3};" \
        : "+f"((d)[0]), "+f"((d)[1]), "+f"((d)[2]), "+f"((d)[3]) \
        : "r"((a)[0]), "r"((a)[1]), "r"((a)[2]), "r"((a)[3]), \
          "r"((b)[0]), "r"((b)[1]))

#define MMAH16816(d, a, b) \
    asm("mma.sync.aligned.m16n8k16.row.col.f32.f16.f16.f32 " \
        "{%0,%1,%2,%3}, {%4,%5,%6,%7}, {%8,%9}, {%0,%1,%2,%3};" \
        : "+f"((d)[0]), "+f"((d)[1]), "+f"((d)[2]), "+f"((d)[3]) \
        : "r"((a)[0]), "r"((a)[1]), "r"((a)[2]), "r"((a)[3]), \
          "r"((b)[0]), "r"((b)[1]))

// ---------------------------------------------------------------------------
// bf16x3 engine (Mt only): 128x128 tile, BK=32, 64B rows, swizzle c^((r>>1)&3).
// fp16 engine: 128x128 tile, BK=64, 128B rows, swizzle c^(r&7).
// Both: 256 threads (8 warps 2x4, 64x32 warp tile), 3-stage cp.async, 2 CTA/SM.
// ---------------------------------------------------------------------------
#define ARR_B 8192                      // bf16x3: 128 rows * 64 B
#define STG_B 32768                     // bf16x3: 4 arrays per stage
#define SMEM_DYN (3 * STG_B)            // 98304
#define ARRF_B 16384                    // fp16: 128 rows * 128 B
#define STGF_B 32768                    // fp16: 2 arrays per stage
#define SMEM_F16 (3 * STGF_B)           // 98304

// 64-byte-row stager (bf16x3 engine)
template <typename T>
__device__ __forceinline__ void stage_arr(uint32_t sdst, const T* __restrict__ src,
                                          int r0, int k0, int ld, int tid) {
#pragma unroll
    for (int j = 0; j < 2; j++) {
        int idx = tid + j * 256;
        int r = idx >> 2, c = idx & 3;
        int phys = c ^ ((r >> 1) & 3);
        uint32_t dst = sdst + (uint32_t)(r * 64 + phys * 16);
        const void* gp = (const void*)(src + (size_t)(r0 + r) * ld + k0 + c * 8);
        asm volatile("cp.async.cg.shared.global [%0], [%1], 16;" :: "r"(dst), "l"(gp));
    }
}

// 128-byte-row stager (fp16 engine, BK=64): 1024 chunks, 8 per row.
__device__ __forceinline__ void stage_arr128(uint32_t sdst, const __half* __restrict__ src,
                                             int r0, int k0, int ld, int tid) {
#pragma unroll
    for (int j = 0; j < 4; j++) {
        int idx = tid + j * 256;
        int r = idx >> 3, c = idx & 7;
        int phys = c ^ (r & 7);
        uint32_t dst = sdst + (uint32_t)(r * 128 + phys * 16);
        const void* gp = (const void*)(src + (size_t)(r0 + r) * ld + k0 + c * 8);
        asm volatile("cp.async.cg.shared.global [%0], [%1], 16;" :: "r"(dst), "l"(gp));
    }
}

// ---------------------------------------------------------------------------
// bf16x3 engine — Mt only.  fp16-out with alpha.
// ---------------------------------------------------------------------------
__device__ __forceinline__ void gemm_bf3(int row0, int col0,
                                         const __nv_bfloat16* __restrict__ Ah,
                                         const __nv_bfloat16* __restrict__ Al,
                                         const __nv_bfloat16* __restrict__ Bh,
                                         const __nv_bfloat16* __restrict__ Bl,
                                         int K, int lda, int ldb, float alpha,
                                         __half* __restrict__ Of, int ldo) {
    extern __shared__ __nv_bfloat16 smem[];

    const int tid  = threadIdx.x;
    const int warp = tid >> 5;
    const int lane = tid & 31;
    const int wm = (warp >> 2) * 64;
    const int wn = (warp & 3) * 32;

    const uint32_t sbase = smem_u32(smem);

    const int aRow = wm + ((lane >> 3) & 1) * 8 + (lane & 7);
    const uint32_t aOff = (uint32_t)(aRow * 64);
    const uint32_t aS   = (uint32_t)((aRow >> 1) & 3);
    const uint32_t aK   = (uint32_t)(lane >> 4);
    const int bRow = wn + ((lane >> 4) & 1) * 8 + (lane & 7);
    const uint32_t bOff = (uint32_t)(bRow * 64);
    const uint32_t bS   = (uint32_t)((bRow >> 1) & 3);
    const uint32_t bK   = (uint32_t)((lane >> 3) & 1);

    float acc[4][4][4];
#pragma unroll
    for (int i = 0; i < 4; i++)
#pragma unroll
        for (int j = 0; j < 4; j++)
#pragma unroll
            for (int e = 0; e < 4; e++) acc[i][j][e] = 0.0f;

    const int niter = K >> 5;

#pragma unroll
    for (int s = 0; s < 2; s++) {
        uint32_t sb = sbase + (uint32_t)(s * STG_B);
        stage_arr(sb + 0 * ARR_B, Ah, row0, s * 32, lda, tid);
        stage_arr(sb + 1 * ARR_B, Al, row0, s * 32, lda, tid);
        stage_arr(sb + 2 * ARR_B, Bh, col0, s * 32, ldb, tid);
        stage_arr(sb + 3 * ARR_B, Bl, col0, s * 32, ldb, tid);
        asm volatile("cp.async.commit_group;" ::: "memory");
    }

    int buf = 0;
    for (int it = 0; it < niter; it++) {
        if (it + 1 < niter) {
            asm volatile("cp.async.wait_group 1;" ::: "memory");
        } else {
            asm volatile("cp.async.wait_group 0;" ::: "memory");
        }
        __syncthreads();
        if (it + 2 < niter) {
            int nb = buf + 2; if (nb >= 3) nb -= 3;
            uint32_t sb = sbase + (uint32_t)(nb * STG_B);
            int k0 = (it + 2) << 5;
            stage_arr(sb + 0 * ARR_B, Ah, row0, k0, lda, tid);
            stage_arr(sb + 1 * ARR_B, Al, row0, k0, lda, tid);
            stage_arr(sb + 2 * ARR_B, Bh, col0, k0, ldb, tid);
            stage_arr(sb + 3 * ARR_B, Bl, col0, k0, ldb, tid);
            asm volatile("cp.async.commit_group;" ::: "memory");
        }

        const uint32_t base = sbase + (uint32_t)(buf * STG_B);
        const uint32_t pAh = base + 0 * ARR_B + aOff;
        const uint32_t pAl = base + 1 * ARR_B + aOff;
        const uint32_t pBh = base + 2 * ARR_B + bOff;
        const uint32_t pBl = base + 3 * ARR_B + bOff;

#pragma unroll
        for (int ks = 0; ks < 2; ks++) {
            const uint32_t koA = (((ks * 2 + aK) ^ aS) << 4);
            const uint32_t koB = (((ks * 2 + bK) ^ bS) << 4);
            uint32_t ah[4][4], al[4][4];
            uint32_t bh[4][2], bl[4][2];
#pragma unroll
            for (int jp = 0; jp < 2; jp++) {
                LDSM4(bh[2 * jp][0], bh[2 * jp][1], bh[2 * jp + 1][0], bh[2 * jp + 1][1],
                      pBh + jp * 1024 + koB);
                LDSM4(bl[2 * jp][0], bl[2 * jp][1], bl[2 * jp + 1][0], bl[2 * jp + 1][1],
                      pBl + jp * 1024 + koB);
            }
#pragma unroll
            for (int i = 0; i < 4; i++) {
                LDSM4(ah[i][0], ah[i][1], ah[i][2], ah[i][3], pAh + i * 1024 + koA);
                LDSM4(al[i][0], al[i][1], al[i][2], al[i][3], pAl + i * 1024 + koA);
            }
#pragma unroll
            for (int i = 0; i < 4; i++)
#pragma unroll
                for (int j = 0; j < 4; j++) MMA16816(acc[i][j], ah[i], bh[j]);
#pragma unroll
            for (int i = 0; i < 4; i++)
#pragma unroll
                for (int j = 0; j < 4; j++) MMA16816(acc[i][j], ah[i], bl[j]);
#pragma unroll
            for (int i = 0; i < 4; i++)
#pragma unroll
                for (int j = 0; j < 4; j++) MMA16816(acc[i][j], al[i], bh[j]);
        }
        buf++; if (buf == 3) buf = 0;
    }

    const int er = lane >> 2;
    const int ec = (lane & 3) * 2;
#pragma unroll
    for (int i = 0; i < 4; i++)
#pragma unroll
        for (int j = 0; j < 4; j++) {
            size_t r = (size_t)(row0 + wm + i * 16 + er);
            int c = col0 + wn + j * 8 + ec;
            *reinterpret_cast<uint32_t*>(&Of[r * ldo + c]) =
                pack_h2(acc[i][j][0] * alpha, acc[i][j][1] * alpha);
            *reinterpret_cast<uint32_t*>(&Of[(r + 8) * ldo + c]) =
                pack_h2(acc[i][j][2] * alpha, acc[i][j][3] * alpha);
        }
}

// ---------------------------------------------------------------------------
// fp16 single-term engine, BK=64 (128B rows, swizzle c^(r&7)).
// MODE 3: fp16 direct store.  MODE 4: fp16 TRANSPOSED store (V^T).
// MODE 5: E = exp(acc) fp16 store + fp32 row-sum atomics.
// MODE 6: fp32 store scaled by 1/rowsum (context; Cf = out, Sf = sums base).
// ---------------------------------------------------------------------------
template <int MODE>
__device__ __forceinline__ void gemm_f16(int row0, int col0,
                                         const __half* __restrict__ Af,
                                         const __half* __restrict__ Bf,
                                         int K, int lda, int ldb,
                                         float* __restrict__ Cf, int ldc,
                                         __half* __restrict__ Of, int ldo,
                                         const float* __restrict__ Sf = nullptr) {
    extern __shared__ __nv_bfloat16 smem[];
    __shared__ float sIs[128];

    const int tid  = threadIdx.x;
    const int warp = tid >> 5;
    const int lane = tid & 31;
    const int wm = (warp >> 2) * 64;
    const int wn = (warp & 3) * 32;

    const uint32_t sbase = smem_u32(smem);

    if constexpr (MODE == 6) {
        if (tid < 128) sIs[tid] = 1.0f / Sf[row0 + tid];
    }

    const int aRow = wm + ((lane >> 3) & 1) * 8 + (lane & 7);
    const uint32_t aOff = (uint32_t)(aRow * 128);
    const uint32_t aS   = (uint32_t)(aRow & 7);
    const uint32_t aK   = (uint32_t)(lane >> 4);
    const int bRow = wn + ((lane >> 4) & 1) * 8 + (lane & 7);
    const uint32_t bOff = (uint32_t)(bRow * 128);
    const uint32_t bS   = (uint32_t)(bRow & 7);
    const uint32_t bK   = (uint32_t)((lane >> 3) & 1);

    float acc[4][4][4];
#pragma unroll
    for (int i = 0; i < 4; i++)
#pragma unroll
        for (int j = 0; j < 4; j++)
#pragma unroll
            for (int e = 0; e < 4; e++) acc[i][j][e] = 0.0f;

    const int niter = K >> 6;

#pragma unroll
    for (int s = 0; s < 2; s++) {
        uint32_t sb = sbase + (uint32_t)(s * STGF_B);
        stage_arr128(sb + 0 * ARRF_B, Af, row0, s * 64, lda, tid);
        stage_arr128(sb + 1 * ARRF_B, Bf, col0, s * 64, ldb, tid);
        asm volatile("cp.async.commit_group;" ::: "memory");
    }

    int buf = 0;
    for (int it = 0; it < niter; it++) {
        if (it + 1 < niter) {
            asm volatile("cp.async.wait_group 1;" ::: "memory");
        } else {
            asm volatile("cp.async.wait_group 0;" ::: "memory");
        }
        __syncthreads();
        if (it + 2 < niter) {
            int nb = buf + 2; if (nb >= 3) nb -= 3;
            uint32_t sb = sbase + (uint32_t)(nb * STGF_B);
            int k0 = (it + 2) << 6;
            stage_arr128(sb + 0 * ARRF_B, Af, row0, k0, lda, tid);
            stage_arr128(sb + 1 * ARRF_B, Bf, col0, k0, ldb, tid);
            asm volatile("cp.async.commit_group;" ::: "memory");
        }

        const uint32_t base = sbase + (uint32_t)(buf * STGF_B);
        const uint32_t pA = base + 0 * ARRF_B + aOff;
        const uint32_t pB = base + 1 * ARRF_B + bOff;

#pragma unroll
        for (int ks = 0; ks < 4; ks++) {
            const uint32_t koA = (((ks * 2 + aK) ^ aS) << 4);
            const uint32_t koB = (((ks * 2 + bK) ^ bS) << 4);
            uint32_t ah[4][4];
            uint32_t bh[4][2];
#pragma unroll
            for (int jp = 0; jp < 2; jp++) {
                LDSM4(bh[2 * jp][0], bh[2 * jp][1], bh[2 * jp + 1][0], bh[2 * jp + 1][1],
                      pB + jp * 2048 + koB);
            }
#pragma unroll
            for (int i = 0; i < 4; i++) {
                LDSM4(ah[i][0], ah[i][1], ah[i][2], ah[i][3], pA + i * 2048 + koA);
            }
#pragma unroll
            for (int i = 0; i < 4; i++)
#pragma unroll
                for (int j = 0; j < 4; j++) MMAH16816(acc[i][j], ah[i], bh[j]);
        }
        buf++; if (buf == 3) buf = 0;
    }

    const int er = lane >> 2;
    const int ec = (lane & 3) * 2;

    if constexpr (MODE == 3) {
#pragma unroll
        for (int i = 0; i < 4; i++)
#pragma unroll
            for (int j = 0; j < 4; j++) {
                size_t r = (size_t)(row0 + wm + i * 16 + er);
                int c = col0 + wn + j * 8 + ec;
                *reinterpret_cast<uint32_t*>(&Of[r * ldo + c]) =
                    pack_h2(acc[i][j][0], acc[i][j][1]);
                *reinterpret_cast<uint32_t*>(&Of[(r + 8) * ldo + c]) =
                    pack_h2(acc[i][j][2], acc[i][j][3]);
            }
    } else if constexpr (MODE == 5) {
        __shared__ float sSum[128];
        if (tid < 128) sSum[tid] = 0.0f;
        __syncthreads();
#pragma unroll
        for (int i = 0; i < 4; i++) {
            float slo = 0.0f, shi = 0.0f;
#pragma unroll
            for (int j = 0; j < 4; j++) {
                float e0 = __expf(acc[i][j][0]), e1 = __expf(acc[i][j][1]);
                float e2 = __expf(acc[i][j][2]), e3 = __expf(acc[i][j][3]);
                size_t r = (size_t)(row0 + wm + i * 16 + er);
                int c = col0 + wn + j * 8 + ec;
                *reinterpret_cast<uint32_t*>(&Of[r * ldo + c])       = pack_h2(e0, e1);
                *reinterpret_cast<uint32_t*>(&Of[(r + 8) * ldo + c]) = pack_h2(e2, e3);
                slo += e0 + e1;
                shi += e2 + e3;
            }
            slo += __shfl_xor_sync(0xffffffffu, slo, 1);
            slo += __shfl_xor_sync(0xffffffffu, slo, 2);
            shi += __shfl_xor_sync(0xffffffffu, shi, 1);
            shi += __shfl_xor_sync(0xffffffffu, shi, 2);
            if ((lane & 3) == 0) {
                atomicAdd(&sSum[wm + i * 16 + er], slo);
                atomicAdd(&sSum[wm + i * 16 + er + 8], shi);
            }
        }
        __syncthreads();
        if (tid < 128) atomicAdd(&Cf[row0 + tid], sSum[tid]);
    } else if constexpr (MODE == 6) {
#pragma unroll
        for (int i = 0; i < 4; i++) {
            float i0 = sIs[wm + i * 16 + er];
            float i1 = sIs[wm + i * 16 + er + 8];
#pragma unroll
            for (int j = 0; j < 4; j++) {
                size_t r = (size_t)(row0 + wm + i * 16 + er);
                int c = col0 + wn + j * 8 + ec;
                *reinterpret_cast<float2*>(&Cf[r * ldc + c]) =
                    make_float2(acc[i][j][0] * i0, acc[i][j][1] * i0);
                *reinterpret_cast<float2*>(&Cf[(r + 8) * ldc + c]) =
                    make_float2(acc[i][j][2] * i1, acc[i][j][3] * i1);
            }
        }
    } else {
        // MODE 4: fp16 transposed store (V^T); row0 indexes tokens [B*S]
        __syncthreads();
        float* ew = (float*)(smem + warp * 768);
        const int b = row0 >> 11;                  // SS == 2048
        __half* Ob = Of + (size_t)b * UU * SS;
#pragma unroll
        for (int i = 0; i < 4; i++)
#pragma unroll
            for (int jp = 0; jp < 2; jp++) {
                int j0 = 2 * jp, j1 = 2 * jp + 1;
                ew[er * 24 + ec]            = acc[i][j0][0];
                ew[er * 24 + ec + 1]        = acc[i][j0][1];
                ew[(er + 8) * 24 + ec]      = acc[i][j0][2];
                ew[(er + 8) * 24 + ec + 1]  = acc[i][j0][3];
                ew[er * 24 + 8 + ec]        = acc[i][j1][0];
                ew[er * 24 + 8 + ec + 1]    = acc[i][j1][1];
                ew[(er + 8) * 24 + 8 + ec]     = acc[i][j1][2];
                ew[(er + 8) * 24 + 8 + ec + 1] = acc[i][j1][3];
                __syncwarp();
                if (lane < 16) {
                    int u = lane;
                    float v[16];
#pragma unroll
                    for (int r = 0; r < 16; r++) v[r] = ew[r * 24 + u];
                    uint32_t hw[8];
#pragma unroll
                    for (int e = 0; e < 8; e++) hw[e] = pack_h2(v[2 * e], v[2 * e + 1]);
                    int s0 = (row0 & 2047) + wm + i * 16;
                    size_t idx = (size_t)(col0 + wn + jp * 16 + u) * SS + s0;
                    uint4 h0, h1;
                    h0.x = hw[0]; h0.y = hw[1]; h0.z = hw[2]; h0.w = hw[3];
                    h1.x = hw[4]; h1.y = hw[5]; h1.z = hw[6]; h1.w = hw[7];
                    *reinterpret_cast<uint4*>(&Ob[idx])     = h0;
                    *reinterpret_cast<uint4*>(&Ob[idx + 8]) = h1;
                }
                __syncwarp();
            }
    }
}

// ---------------------------------------------------------------------------
// GEMM kernel wrappers (2 CTAs/SM)
// ---------------------------------------------------------------------------
__global__ __launch_bounds__(256, 2) void mt_kernel() {
    // Mt fp16 = scale * Wk @ Wq^T  (bf16x3 math, 16 blocks)
    int row0 = ((int)blockIdx.x >> 2) * 128;
    int col0 = ((int)blockIdx.x & 3) * 128;
    gemm_bf3(row0, col0, g_wkh, g_wkl, g_wqh, g_wql, UU, UU, UU, SCALE,
             g_mtf, DD);
}

// Combined: V^T projection (blocks 0..511) + P projection (blocks 512..1023).
__global__ __launch_bounds__(256, 2) void vp_kernel() {
    int id = blockIdx.x;
    if (id < 512) {
        int row0 = (id >> 2) * 128;
        int col0 = (id & 3) * 128;
        gemm_f16<4>(row0, col0, g_xf, g_wvtf, DD, DD, DD,
                    nullptr, 0, g_vtf, SS);
    } else {
        int id2 = id - 512;
        int row0 = (id2 >> 2) * 128;
        int col0 = (id2 & 3) * 128;
        gemm_f16<3>(row0, col0, g_xf, g_mtf, DD, DD, DD,
                    nullptr, 0, g_pf, DD);
    }
}

// scores + exp + row sums fused
__global__ __launch_bounds__(256, 2) void scores_kernel() {
    const size_t z = blockIdx.z;
    gemm_f16<5>(blockIdx.y * 128, blockIdx.x * 128,
                g_pf + z * SS * DD, g_xf + z * SS * DD, DD, DD, DD,
                g_s + z * SS, 0,
                g_af + z * (size_t)SS * SS, SS);
}

__global__ __launch_bounds__(256, 2) void context_kernel(float* __restrict__ ctx) {
    const size_t z = blockIdx.z;
    gemm_f16<6>(blockIdx.y * 128, blockIdx.x * 128,
                g_af + z * (size_t)SS * SS, g_vtf + z * (size_t)UU * SS,
                SS, SS, SS,
                ctx + z * (size_t)SS * UU, UU, nullptr, 0,
                g_s + z * SS);
}

// ---------------------------------------------------------------------------
// Elementwise kernels
// ---------------------------------------------------------------------------
__global__ __launch_bounds__(256) void split_x_kernel(const float* __restrict__ in) {
    int i = blockIdx.x * 256 + threadIdx.x;
    float4 v = reinterpret_cast<const float4*>(in)[i];
    uint2 fp;
    fp.x = pack_h2(v.x, v.y);
    fp.y = pack_h2(v.z, v.w);
    reinterpret_cast<uint2*>(g_xf)[i] = fp;
}

__global__ __launch_bounds__(256) void splitW_kernel(const float* __restrict__ wq,
                                                     const float* __restrict__ wk) {
    const float* src = (blockIdx.y == 0) ? wq : wk;
    __nv_bfloat16* oh = (blockIdx.y == 0) ? g_wqh : g_wkh;
    __nv_bfloat16* ol = (blockIdx.y == 0) ? g_wql : g_wkl;
    int i = blockIdx.x * 256 + threadIdx.x;
    float4 v = reinterpret_cast<const float4*>(src)[i];
    __nv_bfloat16 h0 = __float2bfloat16(v.x), h1 = __float2bfloat16(v.y);
    __nv_bfloat16 h2 = __float2bfloat16(v.z), h3 = __float2bfloat16(v.w);
    uint2 hp, lp;
    hp.x = pack_bf2(h0, h1); hp.y = pack_bf2(h2, h3);
    lp.x = pack_bf2(__float2bfloat16(v.x - __bfloat162float(h0)),
                    __float2bfloat16(v.y - __bfloat162float(h1)));
    lp.y = pack_bf2(__float2bfloat16(v.z - __bfloat162float(h2)),
                    __float2bfloat16(v.w - __bfloat162float(h3)));
    reinterpret_cast<uint2*>(oh)[i] = hp;
    reinterpret_cast<uint2*>(ol)[i] = lp;
}

__global__ void wsplitT_kernel(const float* __restrict__ wv) {
    __shared__ float t[32][33];
    const int u0 = blockIdx.x * 32, d0 = blockIdx.y * 32;
    const int tx = threadIdx.x, ty = threadIdx.y;
#pragma unroll
    for (int p = 0; p < 4; p++)
        t[ty + p * 8][tx] = wv[(size_t)(d0 + ty + p * 8) * UU + u0 + tx];
    __syncthreads();
#pragma unroll
    for (int p = 0; p < 4; p++) {
        float v = t[tx][ty + p * 8];
        size_t idx = (size_t)(u0 + ty + p * 8) * DD + d0 + tx;
        g_wvtf[idx] = __float2half_rn(v);
    }
}

// Final attn: attn[row][c] = E[row][c] / s[row].  2 rows per block.
__global__ __launch_bounds__(256) void normalize_kernel(float* __restrict__ attn) {
    const size_t row = (size_t)blockIdx.x * 2 + (threadIdx.x >> 7);
    const float inv = 1.0f / g_s[row];
    const int c0 = (threadIdx.x & 127) * 16;
    const __half* ep = &g_af[row * SS + c0];
    float* dst = &attn[row * SS + c0];
#pragma unroll
    for (int h = 0; h < 2; h++) {
        uint4 hv = *reinterpret_cast<const uint4*>(ep + h * 8);
        __half2 h0 = *reinterpret_cast<__half2*>(&hv.x);
        __half2 h1 = *reinterpret_cast<__half2*>(&hv.y);
        __half2 h2 = *reinterpret_cast<__half2*>(&hv.z);
        __half2 h3 = *reinterpret_cast<__half2*>(&hv.w);
        float4 f0, f1;
        f0.x = __low2float(h0) * inv; f0.y = __high2float(h0) * inv;
        f0.z = __low2float(h1) * inv; f0.w = __high2float(h1) * inv;
        f1.x = __low2float(h2) * inv; f1.y = __high2float(h2) * inv;
        f1.z = __low2float(h3) * inv; f1.w = __high2float(h3) * inv;
        *reinterpret_cast<float4*>(dst + h * 8)     = f0;
        *reinterpret_cast<float4*>(dst + h * 8 + 4) = f1;
    }
}

// ---------------------------------------------------------------------------
extern "C" void kernel_launch(void* const* d_in, const int* in_sizes, int n_in,
                              void* d_out, int out_size) {
    const float* x  = (const float*)d_in[0];   // [B,S,D]
    const float* wq = (const float*)d_in[1];   // [D,U]
    const float* wk = (const float*)d_in[2];
    const float* wv = (const float*)d_in[3];

    float* out  = (float*)d_out;
    float* ctx  = out;                         // [B,S,U]
    float* attn = out + NX;                    // [B,S,S]

    cudaFuncSetAttribute(mt_kernel,      cudaFuncAttributeMaxDynamicSharedMemorySize, SMEM_DYN);
    cudaFuncSetAttribute(vp_kernel,      cudaFuncAttributeMaxDynamicSharedMemorySize, SMEM_F16);
    cudaFuncSetAttribute(scores_kernel,  cudaFuncAttributeMaxDynamicSharedMemorySize, SMEM_F16);
    cudaFuncSetAttribute(context_kernel, cudaFuncAttributeMaxDynamicSharedMemorySize, SMEM_F16);

    // 0. zero row-sum accumulators (graph-capturable async memset)
    void* sptr = nullptr;
    cudaGetSymbolAddress(&sptr, g_s);
    cudaMemsetAsync(sptr, 0, (size_t)BB * SS * sizeof(float));

    // 1. splits
    splitW_kernel<<<dim3((int)(NW / 4 / 256), 2), 256>>>(wq, wk);
    mt_kernel<<<dim3(16), 256, SMEM_DYN>>>();                 // Mt early (tiny)
    split_x_kernel<<<(int)(NX / 4 / 256), 256>>>(x);
    wsplitT_kernel<<<dim3(UU / 32, DD / 32), dim3(32, 8)>>>(wv);

    // 2. V^T and P in one fp16 launch (1024 blocks)
    vp_kernel<<<dim3(1024), 256, SMEM_F16>>>();

    // 3. E = exp(P @ x^T) fp16 + row sums
    scores_kernel<<<dim3(16, 16, BB), 256, SMEM_F16>>>();

    // 4a. fp32 attn = E / rowsum
    normalize_kernel<<<dim3(BB * SS / 2), 256>>>(attn);

    // 4b. context = (E @ V) / rowsum
    context_kernel<<<dim3(4, 16, BB), 256, SMEM_F16>>>(ctx);
}